// round 11
// baseline (speedup 1.0000x reference)
#include <cuda_runtime.h>
#include <cuda_bf16.h>
#include <cstdint>
#include <cstddef>

#define NHEADS 32
#define HDIM 64
#define MBSZ 16
#define BDIM 4
#define LSEQ 2048
#define CDIM 2048
#define ODIM 768
#define NMB (LSEQ/MBSZ)
#define BL (BDIM*LSEQ)
#define EPSV 1e-6f

// -------- scratch (device globals; no allocations allowed) --------
__device__ float g_xqkv[(size_t)3*BL*CDIM];  // XQ | XK | XV, each [BL, C]
__device__ float g_lr[(size_t)BL*NHEADS];    // lr dot per (token, head)
__device__ float g_Y[(size_t)BL*CDIM];       // scan output, [B,L,C]
// split bf16 operands: per row, per 32-k chunk: 32 hi bf16 then 32 lo bf16 (64 bf16 = 128B)
__device__ __nv_bfloat16 g_Hs[(size_t)BL*2*CDIM];        // H split
__device__ __nv_bfloat16 g_wts[(size_t)3*CDIM*2*CDIM];   // Wq^T|Wk^T|Wv^T split
__device__ __nv_bfloat16 g_wos[(size_t)ODIM*2*CDIM];     // Wo^T split
__device__ __nv_bfloat16 g_Ys[(size_t)BL*2*CDIM];        // post-norm split

// ============================================================
// helpers
// ============================================================
__device__ __forceinline__ uint32_t tfu(float x){
  uint32_t u; asm("cvt.rna.tf32.f32 %0, %1;" : "=r"(u) : "f"(x));
  return u;
}
__device__ __forceinline__ void mma_tf32(float& d0, float& d1, float& d2, float& d3,
                                         uint32_t a0, uint32_t a1, uint32_t a2, uint32_t a3,
                                         uint32_t b0, uint32_t b1){
  asm volatile(
    "mma.sync.aligned.m16n8k8.row.col.f32.tf32.tf32.f32 "
    "{%0,%1,%2,%3}, {%4,%5,%6,%7}, {%8,%9}, {%0,%1,%2,%3};"
    : "+f"(d0), "+f"(d1), "+f"(d2), "+f"(d3)
    : "r"(a0), "r"(a1), "r"(a2), "r"(a3), "r"(b0), "r"(b1));
}
__device__ __forceinline__ void mma_bf16(float& d0, float& d1, float& d2, float& d3,
                                         uint32_t a0, uint32_t a1, uint32_t a2, uint32_t a3,
                                         uint32_t b0, uint32_t b1){
  asm volatile(
    "mma.sync.aligned.m16n8k16.row.col.f32.bf16.bf16.f32 "
    "{%0,%1,%2,%3}, {%4,%5,%6,%7}, {%8,%9}, {%0,%1,%2,%3};"
    : "+f"(d0), "+f"(d1), "+f"(d2), "+f"(d3)
    : "r"(a0), "r"(a1), "r"(a2), "r"(a3), "r"(b0), "r"(b1));
}
__device__ __forceinline__ uint32_t smem_u32(const void* p){
  uint32_t a;
  asm("{ .reg .u64 t; cvta.to.shared.u64 t, %1; cvt.u32.u64 %0, t; }" : "=r"(a) : "l"(p));
  return a;
}
__device__ __forceinline__ void cpa16(uint32_t dst, const void* src){
  asm volatile("cp.async.cg.shared.global [%0], [%1], 16;" :: "r"(dst), "l"(src));
}
__device__ __forceinline__ void cpa_commit(){
  asm volatile("cp.async.commit_group;" ::: "memory");
}

// SMEM tile: per row 64 bf16 (32 hi + 32 lo = 128B) padded to 144B (36 words)
#define A_ST_B (128*144)
#define B_ST_B (256*144)
#define STG_B  (A_ST_B + B_ST_B)
#define NSTG 3
#define SM_GTOT (NSTG*STG_B)

// ============================================================
// split-bf16 GEMM: C[M,Ntot] = A @ Bt^T, operands pre-split hi/lo bf16
// CTA tile 128x256, 8 warps (2m x 4n), warp tile 64x64, 3-term compensation
// ============================================================
__device__ __forceinline__ void gemm_bf16_body(
    const __nv_bfloat16* __restrict__ A, const __nv_bfloat16* __restrict__ Bt,
    float* __restrict__ C, int Ntot, int n0, int cRow)
{
  extern __shared__ float smem[];
  const uint32_t sb = smem_u32(smem);

  const int t    = threadIdx.x;
  const int wid  = t >> 5, lane = t & 31;
  const int wm   = wid & 1;
  const int wn   = wid >> 1;
  const int g    = lane >> 2;
  const int cc   = lane & 3;

  const int ldrow = t >> 3;   // 0..31
  const int ld16  = t & 7;    // 16B unit 0..7 within 128B row

  float d[4][8][4];
  #pragma unroll
  for (int mi=0;mi<4;mi++)
    #pragma unroll
    for (int ni=0;ni<8;ni++)
      #pragma unroll
      for (int r=0;r<4;r++) d[mi][ni][r]=0.f;

  auto issue = [&](int c2, int buf){
    const uint32_t ab = sb + buf*STG_B;
    const uint32_t bb = ab + A_ST_B;
    #pragma unroll
    for (int it=0; it<4; it++){
      int row = ldrow + it*32;
      cpa16(ab + row*144 + ld16*16,
            A + (size_t)(cRow+row)*(2*CDIM) + c2*64 + ld16*8);
    }
    #pragma unroll
    for (int it=0; it<8; it++){
      int row = ldrow + it*32;
      cpa16(bb + row*144 + ld16*16,
            Bt + (size_t)(n0+row)*(2*CDIM) + c2*64 + ld16*8);
    }
    cpa_commit();
  };

  issue(0, 0);
  issue(1, 1);

  for (int c=0; c<64; c++){
    if (c==63) asm volatile("cp.async.wait_group 0;" ::: "memory");
    else       asm volatile("cp.async.wait_group 1;" ::: "memory");
    __syncthreads();
    if (c+2 < 64) issue(c+2, (c+2)%NSTG);

    const uint32_t* As = (const uint32_t*)smem + (c%NSTG)*(STG_B/4);
    const uint32_t* Bs = As + (A_ST_B/4);
    #pragma unroll
    for (int s=0; s<2; s++){
      const int kb = s*8;   // word offset of this k16 within 32-word hi block
      uint32_t ah[4][4], al[4][4];
      #pragma unroll
      for (int mi=0; mi<4; mi++){
        int r0 = wm*64 + mi*16;
        ah[mi][0] = As[(r0 + g    )*36 + kb + cc     ];
        ah[mi][1] = As[(r0 + 8 + g)*36 + kb + cc     ];
        ah[mi][2] = As[(r0 + g    )*36 + kb + cc + 4 ];
        ah[mi][3] = As[(r0 + 8 + g)*36 + kb + cc + 4 ];
        al[mi][0] = As[(r0 + g    )*36 + kb + cc + 16];
        al[mi][1] = As[(r0 + 8 + g)*36 + kb + cc + 16];
        al[mi][2] = As[(r0 + g    )*36 + kb + cc + 20];
        al[mi][3] = As[(r0 + 8 + g)*36 + kb + cc + 20];
      }
      #pragma unroll
      for (int ni=0; ni<8; ni++){
        int nr = wn*64 + ni*8 + g;
        uint32_t bh0 = Bs[nr*36 + kb + cc     ];
        uint32_t bh1 = Bs[nr*36 + kb + cc + 4 ];
        uint32_t bl0 = Bs[nr*36 + kb + cc + 16];
        uint32_t bl1 = Bs[nr*36 + kb + cc + 20];
        #pragma unroll
        for (int mi=0; mi<4; mi++){
          mma_bf16(d[mi][ni][0], d[mi][ni][1], d[mi][ni][2], d[mi][ni][3],
                   ah[mi][0], ah[mi][1], ah[mi][2], ah[mi][3], bh0, bh1);
          mma_bf16(d[mi][ni][0], d[mi][ni][1], d[mi][ni][2], d[mi][ni][3],
                   ah[mi][0], ah[mi][1], ah[mi][2], ah[mi][3], bl0, bl1);
          mma_bf16(d[mi][ni][0], d[mi][ni][1], d[mi][ni][2], d[mi][ni][3],
                   al[mi][0], al[mi][1], al[mi][2], al[mi][3], bh0, bh1);
        }
      }
    }
  }

  #pragma unroll
  for (int mi=0; mi<4; mi++){
    int row = cRow + wm*64 + mi*16 + g;
    #pragma unroll
    for (int ni=0; ni<8; ni++){
      int col = n0 + wn*64 + ni*8 + cc*2;
      *(float2*)(C + (size_t)row*Ntot + col) =
          make_float2(d[mi][ni][0], d[mi][ni][1]);
      *(float2*)(C + (size_t)(row+8)*Ntot + col) =
          make_float2(d[mi][ni][2], d[mi][ni][3]);
    }
  }
}

__global__ __launch_bounds__(256,1) void gemm_qkv_bf16(){
  const int z = blockIdx.x >> 3;
  const int n = blockIdx.x & 7;
  const __nv_bfloat16* Bt = g_wts + (size_t)z * CDIM * 2*CDIM;
  float* Cc = g_xqkv + (size_t)z * (size_t)BL * CDIM;
  gemm_bf16_body(g_Hs, Bt, Cc, CDIM, n*256, blockIdx.y*128);
}
__global__ __launch_bounds__(256,1) void gemm_out_bf16(float* __restrict__ out){
  gemm_bf16_body(g_Ys, g_wos, out, ODIM, blockIdx.x*256, blockIdx.y*128);
}

// ============================================================
// prep: transpose + hi/lo split. in[R][C] fp32 -> out rows = C, K = R (split layout)
// ============================================================
__global__ __launch_bounds__(256) void transpose_split(
    const float* __restrict__ in, __nv_bfloat16* __restrict__ out, int R, int C)
{
  __shared__ float tile[32][33];
  int c0 = blockIdx.x*32, r0 = blockIdx.y*32;
  int tx = threadIdx.x & 31, ty = threadIdx.x >> 5;
  for (int i=ty; i<32; i+=8) tile[i][tx] = in[(size_t)(r0+i)*C + c0 + tx];
  __syncthreads();
  for (int i=ty; i<32; i+=8){
    float v = tile[tx][i];
    __nv_bfloat16 hi = __float2bfloat16(v);
    __nv_bfloat16 lo = __float2bfloat16(v - __bfloat162float(hi));
    int k = r0 + tx;
    size_t base = (size_t)(c0+i)*(2*R) + (k>>5)*64 + (k&31);
    out[base]      = hi;
    out[base + 32] = lo;
  }
}

// split H -> g_Hs
__global__ __launch_bounds__(256) void split_H(const float* __restrict__ in){
  size_t fi = ((size_t)blockIdx.x*256 + threadIdx.x)*4;
  int row = (int)(fi >> 11);
  int k   = (int)(fi & 2047);
  float4 v = *(const float4*)(in + fi);
  __nv_bfloat16* hp = g_Hs + (size_t)row*(2*CDIM) + (k>>5)*64 + (k&31);
  float a[4] = {v.x, v.y, v.z, v.w};
  #pragma unroll
  for (int j=0;j<4;j++){
    __nv_bfloat16 hi = __float2bfloat16(a[j]);
    hp[j]    = hi;
    hp[32+j] = __float2bfloat16(a[j] - __bfloat162float(hi));
  }
}

// ============================================================
// lr dot: out[row, h] = sum_c X[row,c] * lrw[h,c]
// ============================================================
__global__ __launch_bounds__(256) void lr_gemm(
    const float* __restrict__ X, const float* __restrict__ Wl)
{
  __shared__ float Xs[64][65];
  __shared__ float Ws[64][33];
  int t = threadIdx.x;
  int row0 = blockIdx.x * 64;
  float acc[8];
  #pragma unroll
  for (int r=0;r<8;r++) acc[r]=0.f;
  int rBase = (t >> 5) * 8;
  int hCol  = t & 31;
  for (int k0=0;k0<CDIM;k0+=64){
    for (int e=t;e<1024;e+=256){
      int r = e >> 4; int c4 = (e & 15)*4;
      float4 v = *(const float4*)(X + (size_t)(row0+r)*CDIM + k0 + c4);
      Xs[r][c4+0]=v.x; Xs[r][c4+1]=v.y; Xs[r][c4+2]=v.z; Xs[r][c4+3]=v.w;
    }
    for (int e=t;e<512;e+=256){
      int hh = e >> 4; int c4 = (e & 15)*4;
      float4 v = *(const float4*)(Wl + (size_t)hh*CDIM + k0 + c4);
      Ws[c4+0][hh]=v.x; Ws[c4+1][hh]=v.y; Ws[c4+2][hh]=v.z; Ws[c4+3][hh]=v.w;
    }
    __syncthreads();
    #pragma unroll 16
    for (int k=0;k<64;k++){
      float w = Ws[k][hCol];
      #pragma unroll
      for (int r=0;r<8;r++) acc[r] = fmaf(Xs[rBase+r][k], w, acc[r]);
    }
    __syncthreads();
  }
  #pragma unroll
  for (int r=0;r<8;r++)
    g_lr[(size_t)(row0+rBase+r)*NHEADS + hCol] = acc[r];
}

// ============================================================
// TTT scan: one block per (b,h). 128 sequential mini-batch steps.
// GEMM-lets on mma.sync tf32 tensor cores (validated R10).
// ============================================================
__global__ __launch_bounds__(256) void ttt_scan(
  const int*   __restrict__ pid,
  const float* __restrict__ W1in, const float* __restrict__ b1in,
  const float* __restrict__ lrb,  const float* __restrict__ ltid,
  const float* __restrict__ lnw,  const float* __restrict__ lnb)
{
  int b = blockIdx.x >> 5;
  int h = blockIdx.x & 31;
  __shared__ float W1s[64][72];
  __shared__ float gr[16][72];
  __shared__ float xq[16][68], xk[16][68], xv[16][68], zz[16][68];
  __shared__ float attn[16][20], Smat[16][20];
  __shared__ float b1s[64], gam[64], bet[64];
  __shared__ float etalr[16], ce[16], tok[16];
  __shared__ float ctab[16][32], stab[16][32];
  int t = threadIdx.x;
  int w = t >> 5, lane = t & 31;
  int g = lane >> 2, cc = lane & 3;

  for (int e=t;e<4096;e+=256) W1s[e>>6][e&63] = W1in[(size_t)h*4096 + e];
  if (t<64){ b1s[t]=b1in[h*64+t]; gam[t]=lnw[h*64+t]; bet[t]=lnb[h*64+t]; }
  if (t<16) tok[t] = fmaxf(1.f/(float)(t+1) + ltid[t], 0.f);
  for (int e=t;e<512;e+=256){
    int p = e >> 5, pi = e & 31;
    float inv = exp2f(-13.287712379549449f * (float)(2*pi) * (1.f/64.f));
    float ang = (float)p * inv;
    ctab[p][pi] = cosf(ang); stab[p][pi] = sinf(ang);
  }
  float lrbias = lrb[h];
  __syncthreads();

  const size_t PL = (size_t)BL*CDIM;
  const float* XQp = g_xqkv;
  const float* XKp = g_xqkv + PL;
  const float* XVp = g_xqkv + 2*PL;

  for (int m=0;m<NMB;m++){
    int l0 = m*MBSZ;
    for (int p=t;p<512;p+=256){
      int i = p >> 5, pi = p & 31;
      size_t base = ((size_t)b*LSEQ + l0 + i)*CDIM + h*64 + 2*pi;
      int pos = pid[(size_t)b*LSEQ + l0 + i] & 15;
      float c = ctab[pos][pi], s = stab[pos][pi];
      float q0=XQp[base], q1=XQp[base+1];
      xq[i][2*pi]   = q0*c - q1*s;
      xq[i][2*pi+1] = q1*c + q0*s;
      float k0=XKp[base], k1=XKp[base+1];
      xk[i][2*pi]   = k0*c - k1*s;
      xk[i][2*pi+1] = k1*c + k0*s;
    }
    for (int e=t;e<512;e+=256){
      int i = e >> 5, d2 = (e & 31)*2;
      float2 v = *(const float2*)(XVp + ((size_t)b*LSEQ + l0 + i)*CDIM + h*64 + d2);
      xv[i][d2] = v.x; xv[i][d2+1] = v.y;
    }
    if (t<16){
      float x = g_lr[((size_t)b*LSEQ + l0 + t)*NHEADS + h] + lrbias;
      float e = (1.f/(1.f+expf(-x))) * (1.f/64.f);
      etalr[t]=e; ce[t]=tok[15]*e;
    }
    __syncthreads();
    {
      const int n0 = w*8;
      float d0 = b1s[n0+2*cc], d1 = b1s[n0+2*cc+1];
      float d2 = d0, d3 = d1;
      #pragma unroll
      for (int ks=0; ks<8; ks++){
        const int kk = ks*8;
        uint32_t a0 = tfu(xk[g  ][kk+cc  ]), a1 = tfu(xk[8+g][kk+cc  ]);
        uint32_t a2 = tfu(xk[g  ][kk+cc+4]), a3 = tfu(xk[8+g][kk+cc+4]);
        uint32_t b0 = tfu(W1s[kk+cc][n0+g]), b1f= tfu(W1s[kk+cc+4][n0+g]);
        mma_tf32(d0,d1,d2,d3, a0,a1,a2,a3, b0,b1f);
      }
      zz[g  ][n0+2*cc]=d0; zz[g  ][n0+2*cc+1]=d1;
      zz[8+g][n0+2*cc]=d2; zz[8+g][n0+2*cc+1]=d3;
      if (w < 2){
        const int na = w*8;
        float e0=0.f,e1=0.f,e2=0.f,e3=0.f;
        #pragma unroll
        for (int ks=0; ks<8; ks++){
          const int kk = ks*8;
          uint32_t a0 = tfu(xq[g  ][kk+cc  ]), a1 = tfu(xq[8+g][kk+cc  ]);
          uint32_t a2 = tfu(xq[g  ][kk+cc+4]), a3 = tfu(xq[8+g][kk+cc+4]);
          uint32_t b0 = tfu(xk[na+g][kk+cc ]), b1f= tfu(xk[na+g][kk+cc+4]);
          mma_tf32(e0,e1,e2,e3, a0,a1,a2,a3, b0,b1f);
        }
        attn[g  ][na+2*cc]=e0; attn[g  ][na+2*cc+1]=e1;
        attn[8+g][na+2*cc]=e2; attn[8+g][na+2*cc+1]=e3;
      }
    }
    __syncthreads();
    {
      int i = t >> 4, j = t & 15;
      Smat[i][j] = (j <= i) ? -tok[i]*etalr[j]*(attn[i][j] + 1.f) : 0.f;
    }
    {
      for (int i=w;i<16;i+=8){
        float v0 = zz[i][lane], v1 = zz[i][lane+32];
        float sm = v0+v1, sq = v0*v0+v1*v1;
        #pragma unroll
        for (int o=16;o;o>>=1){ sm += __shfl_xor_sync(~0u, sm, o); sq += __shfl_xor_sync(~0u, sq, o); }
        float mu = sm * (1.f/64.f);
        float var = sq * (1.f/64.f) - mu*mu;
        float rstd = rsqrtf(var + EPSV);
        float xh0 = (v0-mu)*rstd, xh1 = (v1-mu)*rstd;
        float g0 = gam[lane], g1 = gam[lane+32];
        float y0 = g0*xh0 + bet[lane], y1 = g1*xh1 + bet[lane+32];
        float tg0 = (y0 - (xv[i][lane]    - xk[i][lane]   )) * g0;
        float tg1 = (y1 - (xv[i][lane+32] - xk[i][lane+32])) * g1;
        float sg = tg0+tg1, sgx = tg0*xh0 + tg1*xh1;
        #pragma unroll
        for (int o=16;o;o>>=1){ sg += __shfl_xor_sync(~0u, sg, o); sgx += __shfl_xor_sync(~0u, sgx, o); }
        float sc = rstd * (1.f/64.f);
        gr[i][lane]    = (64.f*tg0 - sg - xh0*sgx) * sc;
        gr[i][lane+32] = (64.f*tg1 - sg - xh1*sgx) * sc;
      }
    }
    __syncthreads();
    {
      const int n0 = w*8;
      float d0 = b1s[n0+2*cc], d1 = b1s[n0+2*cc+1];
      float d2 = d0, d3 = d1;
      #pragma unroll
      for (int ks=0; ks<8; ks++){
        const int kk = ks*8;
        uint32_t a0 = tfu(xq[g  ][kk+cc  ]), a1 = tfu(xq[8+g][kk+cc  ]);
        uint32_t a2 = tfu(xq[g  ][kk+cc+4]), a3 = tfu(xq[8+g][kk+cc+4]);
        uint32_t b0 = tfu(W1s[kk+cc][n0+g]), b1f= tfu(W1s[kk+cc+4][n0+g]);
        mma_tf32(d0,d1,d2,d3, a0,a1,a2,a3, b0,b1f);
      }
      #pragma unroll
      for (int ks=0; ks<2; ks++){
        const int kk = ks*8;
        uint32_t a0 = tfu(Smat[g  ][kk+cc  ]), a1 = tfu(Smat[8+g][kk+cc  ]);
        uint32_t a2 = tfu(Smat[g  ][kk+cc+4]), a3 = tfu(Smat[8+g][kk+cc+4]);
        uint32_t b0 = tfu(gr[kk+cc][n0+g]),   b1f= tfu(gr[kk+cc+4][n0+g]);
        mma_tf32(d0,d1,d2,d3, a0,a1,a2,a3, b0,b1f);
      }
      zz[g  ][n0+2*cc]=d0; zz[g  ][n0+2*cc+1]=d1;
      zz[8+g][n0+2*cc]=d2; zz[8+g][n0+2*cc+1]=d3;
    }
    __syncthreads();
    {
      for (int i=w;i<16;i+=8){
        float v0 = zz[i][lane], v1 = zz[i][lane+32];
        float sm = v0+v1, sq = v0*v0+v1*v1;
        #pragma unroll
        for (int o=16;o;o>>=1){ sm += __shfl_xor_sync(~0u, sm, o); sq += __shfl_xor_sync(~0u, sq, o); }
        float mu = sm*(1.f/64.f);
        float rstd = rsqrtf(sq*(1.f/64.f) - mu*mu + EPSV);
        size_t orow = ((size_t)b*LSEQ + l0 + i)*CDIM + h*64;
        g_Y[orow+lane]    = xq[i][lane]    + gam[lane]   *((v0-mu)*rstd) + bet[lane];
        g_Y[orow+lane+32] = xq[i][lane+32] + gam[lane+32]*((v1-mu)*rstd) + bet[lane+32];
      }
      const int m0 = 16*(w & 3);
      uint32_t ua[2][4];
      #pragma unroll
      for (int ks=0; ks<2; ks++){
        const int kk = ks*8;
        ua[ks][0] = tfu(-ce[kk+cc  ] * xk[kk+cc  ][m0+g  ]);
        ua[ks][1] = tfu(-ce[kk+cc  ] * xk[kk+cc  ][m0+8+g]);
        ua[ks][2] = tfu(-ce[kk+cc+4] * xk[kk+cc+4][m0+g  ]);
        ua[ks][3] = tfu(-ce[kk+cc+4] * xk[kk+cc+4][m0+8+g]);
      }
      #pragma unroll
      for (int nt=0; nt<4; nt++){
        const int nu = 32*(w>>2) + 8*nt;
        float d0 = W1s[m0+g  ][nu+2*cc], d1 = W1s[m0+g  ][nu+2*cc+1];
        float d2 = W1s[m0+8+g][nu+2*cc], d3 = W1s[m0+8+g][nu+2*cc+1];
        #pragma unroll
        for (int ks=0; ks<2; ks++){
          const int kk = ks*8;
          uint32_t b0 = tfu(gr[kk+cc][nu+g]), b1f = tfu(gr[kk+cc+4][nu+g]);
          mma_tf32(d0,d1,d2,d3, ua[ks][0],ua[ks][1],ua[ks][2],ua[ks][3], b0,b1f);
        }
        W1s[m0+g  ][nu+2*cc]=d0; W1s[m0+g  ][nu+2*cc+1]=d1;
        W1s[m0+8+g][nu+2*cc]=d2; W1s[m0+8+g][nu+2*cc+1]=d3;
      }
      if (t<64){
        float a = b1s[t];
        #pragma unroll
        for (int j=0;j<16;j++) a = fmaf(-ce[j], gr[j][t], a);
        b1s[t] = a;
      }
    }
    __syncthreads();
  }
}

// ============================================================
// Post layernorm over C=2048 per row -> split bf16 for out-GEMM
// ============================================================
__global__ __launch_bounds__(256) void rownorm(
    const float* __restrict__ w, const float* __restrict__ bias)
{
  int row = blockIdx.x; int t = threadIdx.x;
  const float* rp = g_Y + (size_t)row * CDIM;
  float s=0.f, ss=0.f;
  for (int c=t;c<CDIM;c+=256){ float v = rp[c]; s+=v; ss=fmaf(v,v,ss); }
  #pragma unroll
  for (int o=16;o;o>>=1){ s += __shfl_xor_sync(~0u,s,o); ss += __shfl_xor_sync(~0u,ss,o); }
  __shared__ float sw[8], ssw[8];
  int wid=t>>5, lane=t&31;
  if (lane==0){ sw[wid]=s; ssw[wid]=ss; }
  __syncthreads();
  float ts=0.f, tss=0.f;
  #pragma unroll
  for (int i2=0;i2<8;i2++){ ts+=sw[i2]; tss+=ssw[i2]; }
  float mu = ts*(1.f/CDIM);
  float rstd = rsqrtf(tss*(1.f/CDIM) - mu*mu + EPSV);
  __nv_bfloat16* op = g_Ys + (size_t)row*(2*CDIM);
  for (int c=t;c<CDIM;c+=256){
    float y = (rp[c]-mu)*rstd*w[c] + bias[c];
    __nv_bfloat16 hi = __float2bfloat16(y);
    size_t base = (size_t)(c>>5)*64 + (c&31);
    op[base]      = hi;
    op[base + 32] = __float2bfloat16(y - __bfloat162float(hi));
  }
}

// ============================================================
extern "C" void kernel_launch(void* const* d_in, const int* in_sizes, int n_in,
                              void* d_out, int out_size)
{
  const float* H   = (const float*)d_in[0];
  const int*   pid = (const int*)  d_in[1];
  const float* Wq  = (const float*)d_in[2];
  const float* Wk  = (const float*)d_in[3];
  const float* Wv  = (const float*)d_in[4];
  const float* Wo  = (const float*)d_in[5];
  const float* W1  = (const float*)d_in[6];
  const float* b1  = (const float*)d_in[7];
  const float* lrw = (const float*)d_in[8];
  const float* lrb = (const float*)d_in[9];
  const float* lti = (const float*)d_in[10];
  const float* lnw = (const float*)d_in[11];
  const float* lnb = (const float*)d_in[12];
  const float* pnw = (const float*)d_in[13];
  const float* pnb = (const float*)d_in[14];
  float* out = (float*)d_out;
  (void)in_sizes; (void)n_in; (void)out_size;

  static bool attr_set = false;
  if (!attr_set){
    cudaFuncSetAttribute(gemm_qkv_bf16, cudaFuncAttributeMaxDynamicSharedMemorySize, SM_GTOT);
    cudaFuncSetAttribute(gemm_out_bf16, cudaFuncAttributeMaxDynamicSharedMemorySize, SM_GTOT);
    attr_set = true;
  }

  __nv_bfloat16* wts = nullptr; cudaGetSymbolAddress((void**)&wts, g_wts);
  __nv_bfloat16* wos = nullptr; cudaGetSymbolAddress((void**)&wos, g_wos);

  transpose_split<<<dim3(64,64), 256>>>(Wq, wts,                            CDIM, CDIM);
  transpose_split<<<dim3(64,64), 256>>>(Wk, wts + (size_t)CDIM*2*CDIM,      CDIM, CDIM);
  transpose_split<<<dim3(64,64), 256>>>(Wv, wts + (size_t)2*CDIM*2*CDIM,    CDIM, CDIM);
  transpose_split<<<dim3(24,64), 256>>>(Wo, wos,                            CDIM, ODIM);
  split_H<<<(BL*(size_t)CDIM)/(256*4), 256>>>(H);

  gemm_qkv_bf16<<<dim3(24, BL/128), 256, SM_GTOT>>>();
  lr_gemm<<<BL/64, 256>>>(H, lrw);
  ttt_scan<<<BDIM*NHEADS, 256>>>(pid, W1, b1, lrb, lti, lnw, lnb);
  rownorm<<<BL, 256>>>(pnw, pnb);
  gemm_out_bf16<<<dim3(ODIM/256, BL/128), 256, SM_GTOT>>>(out);
}

// round 13
// speedup vs baseline: 1.0214x; 1.0214x over previous
#include <cuda_runtime.h>
#include <cuda_bf16.h>
#include <cstdint>
#include <cstddef>

#define NHEADS 32
#define HDIM 64
#define MBSZ 16
#define BDIM 4
#define LSEQ 2048
#define CDIM 2048
#define ODIM 768
#define NMB (LSEQ/MBSZ)
#define BL (BDIM*LSEQ)
#define EPSV 1e-6f

// -------- scratch (device globals; no allocations allowed) --------
__device__ float g_xqkv[(size_t)3*BL*CDIM];  // XQ | XK | XV, each [BL, C]
__device__ float g_lr[(size_t)BL*NHEADS];    // lr dot per (token, head)
__device__ float g_Y[(size_t)BL*CDIM];       // scan output, [B,L,C]
// split bf16 operands: per row, per 32-k chunk: 32 hi bf16 then 32 lo bf16 (64 bf16 = 128B)
__device__ __nv_bfloat16 g_Hs[(size_t)BL*2*CDIM];        // H split
__device__ __nv_bfloat16 g_wts[(size_t)3*CDIM*2*CDIM];   // Wq^T|Wk^T|Wv^T split
__device__ __nv_bfloat16 g_wos[(size_t)ODIM*2*CDIM];     // Wo^T split
__device__ __nv_bfloat16 g_Ys[(size_t)BL*2*CDIM];        // post-norm split

// ============================================================
// helpers
// ============================================================
__device__ __forceinline__ uint32_t tfu(float x){
  uint32_t u; asm("cvt.rna.tf32.f32 %0, %1;" : "=r"(u) : "f"(x));
  return u;
}
__device__ __forceinline__ void mma_tf32(float& d0, float& d1, float& d2, float& d3,
                                         uint32_t a0, uint32_t a1, uint32_t a2, uint32_t a3,
                                         uint32_t b0, uint32_t b1){
  asm volatile(
    "mma.sync.aligned.m16n8k8.row.col.f32.tf32.tf32.f32 "
    "{%0,%1,%2,%3}, {%4,%5,%6,%7}, {%8,%9}, {%0,%1,%2,%3};"
    : "+f"(d0), "+f"(d1), "+f"(d2), "+f"(d3)
    : "r"(a0), "r"(a1), "r"(a2), "r"(a3), "r"(b0), "r"(b1));
}
__device__ __forceinline__ void mma_bf16(float& d0, float& d1, float& d2, float& d3,
                                         uint32_t a0, uint32_t a1, uint32_t a2, uint32_t a3,
                                         uint32_t b0, uint32_t b1){
  asm volatile(
    "mma.sync.aligned.m16n8k16.row.col.f32.bf16.bf16.f32 "
    "{%0,%1,%2,%3}, {%4,%5,%6,%7}, {%8,%9}, {%0,%1,%2,%3};"
    : "+f"(d0), "+f"(d1), "+f"(d2), "+f"(d3)
    : "r"(a0), "r"(a1), "r"(a2), "r"(a3), "r"(b0), "r"(b1));
}
__device__ __forceinline__ void ldm4(uint32_t& r0, uint32_t& r1, uint32_t& r2, uint32_t& r3,
                                     uint32_t addr){
  asm volatile("ldmatrix.sync.aligned.m8n8.x4.shared.b16 {%0,%1,%2,%3}, [%4];"
    : "=r"(r0), "=r"(r1), "=r"(r2), "=r"(r3) : "r"(addr));
}
__device__ __forceinline__ uint32_t smem_u32(const void* p){
  uint32_t a;
  asm("{ .reg .u64 t; cvta.to.shared.u64 t, %1; cvt.u32.u64 %0, t; }" : "=r"(a) : "l"(p));
  return a;
}
__device__ __forceinline__ void cpa16(uint32_t dst, const void* src){
  asm volatile("cp.async.cg.shared.global [%0], [%1], 16;" :: "r"(dst), "l"(src));
}
__device__ __forceinline__ void cpa_commit(){
  asm volatile("cp.async.commit_group;" ::: "memory");
}

// SMEM tile: per row 64 bf16 (32 hi + 32 lo = 128B) padded to 144B
#define A_ST_B (128*144)
#define B_ST_B (256*144)
#define STG_B  (A_ST_B + B_ST_B)
#define NSTG 3
#define SM_GTOT (NSTG*STG_B)

// ============================================================
// split-bf16 GEMM: C[M,Ntot] = A @ Bt^T, operands pre-split hi/lo bf16
// CTA tile 128x256, 8 warps (2m x 4n), warp tile 64x64.
// 3-term compensation: Ah*Bh + Ah*Bl + Al*Bh. Fragments via ldmatrix.x4.
// ============================================================
__device__ __forceinline__ void gemm_bf16_body(
    const __nv_bfloat16* __restrict__ A, const __nv_bfloat16* __restrict__ Bt,
    float* __restrict__ C, int Ntot, int n0, int cRow)
{
  extern __shared__ float smem[];
  const uint32_t sb = smem_u32(smem);

  const int t    = threadIdx.x;
  const int wid  = t >> 5, lane = t & 31;
  const int wm   = wid & 1;
  const int wn   = wid >> 1;
  const int g    = lane >> 2;
  const int cc   = lane & 3;

  const int ldrow = t >> 3;   // 0..31
  const int ld16  = t & 7;    // 16B unit within 128B row

  // ldmatrix per-thread address offsets (within a stage)
  // A x4 mats: (m0-7,k0-7)(m8-15,k0-7)(m0-7,k8-15)(m8-15,k8-15)
  const int aoff = (wm*64 + (lane & 15))*144 + ((lane & 16) ? 16 : 0);
  // B x4 mats: (n0-7,k0-7)(n0-7,k8-15)(n8-15,k0-7)(n8-15,k8-15)
  const int boff = (wn*64 + ((lane & 16) ? 8 : 0) + (lane & 7))*144 + ((lane & 8) ? 16 : 0);

  float d[4][8][4];
  #pragma unroll
  for (int mi=0;mi<4;mi++)
    #pragma unroll
    for (int ni=0;ni<8;ni++)
      #pragma unroll
      for (int r=0;r<4;r++) d[mi][ni][r]=0.f;

  auto issue = [&](int c2, int buf){
    const uint32_t ab = sb + buf*STG_B;
    const uint32_t bb = ab + A_ST_B;
    #pragma unroll
    for (int it=0; it<4; it++){
      int row = ldrow + it*32;
      cpa16(ab + row*144 + ld16*16,
            A + (size_t)(cRow+row)*(2*CDIM) + c2*64 + ld16*8);
    }
    #pragma unroll
    for (int it=0; it<8; it++){
      int row = ldrow + it*32;
      cpa16(bb + row*144 + ld16*16,
            Bt + (size_t)(n0+row)*(2*CDIM) + c2*64 + ld16*8);
    }
    cpa_commit();
  };

  issue(0, 0);
  issue(1, 1);

  for (int c=0; c<64; c++){
    if (c==63) asm volatile("cp.async.wait_group 0;" ::: "memory");
    else       asm volatile("cp.async.wait_group 1;" ::: "memory");
    __syncthreads();
    if (c+2 < 64) issue(c+2, (c+2)%NSTG);

    const uint32_t stb = sb + (c%NSTG)*STG_B;
    const uint32_t ab  = stb + aoff;
    const uint32_t bb  = stb + A_ST_B + boff;

    #pragma unroll
    for (int s=0; s<2; s++){
      uint32_t ah[4][4], al[4][4];
      #pragma unroll
      for (int mi=0; mi<4; mi++){
        ldm4(ah[mi][0], ah[mi][1], ah[mi][2], ah[mi][3], ab + mi*2304 + s*32);
        ldm4(al[mi][0], al[mi][1], al[mi][2], al[mi][3], ab + mi*2304 + s*32 + 64);
      }
      #pragma unroll
      for (int pr=0; pr<4; pr++){
        uint32_t bh0,bh1,bh2,bh3, bl0,bl1,bl2,bl3;
        ldm4(bh0, bh1, bh2, bh3, bb + pr*2304 + s*32);
        ldm4(bl0, bl1, bl2, bl3, bb + pr*2304 + s*32 + 64);
        const int n0i = 2*pr, n1i = 2*pr+1;
        #pragma unroll
        for (int mi=0; mi<4; mi++){
          mma_bf16(d[mi][n0i][0], d[mi][n0i][1], d[mi][n0i][2], d[mi][n0i][3],
                   ah[mi][0], ah[mi][1], ah[mi][2], ah[mi][3], bh0, bh1);
          mma_bf16(d[mi][n0i][0], d[mi][n0i][1], d[mi][n0i][2], d[mi][n0i][3],
                   ah[mi][0], ah[mi][1], ah[mi][2], ah[mi][3], bl0, bl1);
          mma_bf16(d[mi][n0i][0], d[mi][n0i][1], d[mi][n0i][2], d[mi][n0i][3],
                   al[mi][0], al[mi][1], al[mi][2], al[mi][3], bh0, bh1);
          mma_bf16(d[mi][n1i][0], d[mi][n1i][1], d[mi][n1i][2], d[mi][n1i][3],
                   ah[mi][0], ah[mi][1], ah[mi][2], ah[mi][3], bh2, bh3);
          mma_bf16(d[mi][n1i][0], d[mi][n1i][1], d[mi][n1i][2], d[mi][n1i][3],
                   ah[mi][0], ah[mi][1], ah[mi][2], ah[mi][3], bl2, bl3);
          mma_bf16(d[mi][n1i][0], d[mi][n1i][1], d[mi][n1i][2], d[mi][n1i][3],
                   al[mi][0], al[mi][1], al[mi][2], al[mi][3], bh2, bh3);
        }
      }
    }
  }

  #pragma unroll
  for (int mi=0; mi<4; mi++){
    int row = cRow + wm*64 + mi*16 + g;
    #pragma unroll
    for (int ni=0; ni<8; ni++){
      int col = n0 + wn*64 + ni*8 + cc*2;
      *(float2*)(C + (size_t)row*Ntot + col) =
          make_float2(d[mi][ni][0], d[mi][ni][1]);
      *(float2*)(C + (size_t)(row+8)*Ntot + col) =
          make_float2(d[mi][ni][2], d[mi][ni][3]);
    }
  }
}

__global__ __launch_bounds__(256,1) void gemm_qkv_bf16(){
  const int z = blockIdx.x >> 3;
  const int n = blockIdx.x & 7;
  const __nv_bfloat16* Bt = g_wts + (size_t)z * CDIM * 2*CDIM;
  float* Cc = g_xqkv + (size_t)z * (size_t)BL * CDIM;
  gemm_bf16_body(g_Hs, Bt, Cc, CDIM, n*256, blockIdx.y*128);
}
__global__ __launch_bounds__(256,1) void gemm_out_bf16(float* __restrict__ out){
  gemm_bf16_body(g_Ys, g_wos, out, ODIM, blockIdx.x*256, blockIdx.y*128);
}

// ============================================================
// prep: transpose + hi/lo split. in[R][C] fp32 -> out rows = C, K = R
// ============================================================
__global__ __launch_bounds__(256) void transpose_split(
    const float* __restrict__ in, __nv_bfloat16* __restrict__ out, int R, int C)
{
  __shared__ float tile[32][33];
  int c0 = blockIdx.x*32, r0 = blockIdx.y*32;
  int tx = threadIdx.x & 31, ty = threadIdx.x >> 5;
  for (int i=ty; i<32; i+=8) tile[i][tx] = in[(size_t)(r0+i)*C + c0 + tx];
  __syncthreads();
  for (int i=ty; i<32; i+=8){
    float v = tile[tx][i];
    __nv_bfloat16 hi = __float2bfloat16(v);
    __nv_bfloat16 lo = __float2bfloat16(v - __bfloat162float(hi));
    int k = r0 + tx;
    size_t base = (size_t)(c0+i)*(2*R) + (k>>5)*64 + (k&31);
    out[base]      = hi;
    out[base + 32] = lo;
  }
}

// split H -> g_Hs
__global__ __launch_bounds__(256) void split_H(const float* __restrict__ in){
  size_t fi = ((size_t)blockIdx.x*256 + threadIdx.x)*4;
  int row = (int)(fi >> 11);
  int k   = (int)(fi & 2047);
  float4 v = *(const float4*)(in + fi);
  __nv_bfloat16* hp = g_Hs + (size_t)row*(2*CDIM) + (k>>5)*64 + (k&31);
  float a[4] = {v.x, v.y, v.z, v.w};
  #pragma unroll
  for (int j=0;j<4;j++){
    __nv_bfloat16 hi = __float2bfloat16(a[j]);
    hp[j]    = hi;
    hp[32+j] = __float2bfloat16(a[j] - __bfloat162float(hi));
  }
}

// ============================================================
// lr dot: out[row, h] = sum_c X[row,c] * lrw[h,c]
// ============================================================
__global__ __launch_bounds__(256) void lr_gemm(
    const float* __restrict__ X, const float* __restrict__ Wl)
{
  __shared__ float Xs[64][65];
  __shared__ float Ws[64][33];
  int t = threadIdx.x;
  int row0 = blockIdx.x * 64;
  float acc[8];
  #pragma unroll
  for (int r=0;r<8;r++) acc[r]=0.f;
  int rBase = (t >> 5) * 8;
  int hCol  = t & 31;
  for (int k0=0;k0<CDIM;k0+=64){
    for (int e=t;e<1024;e+=256){
      int r = e >> 4; int c4 = (e & 15)*4;
      float4 v = *(const float4*)(X + (size_t)(row0+r)*CDIM + k0 + c4);
      Xs[r][c4+0]=v.x; Xs[r][c4+1]=v.y; Xs[r][c4+2]=v.z; Xs[r][c4+3]=v.w;
    }
    for (int e=t;e<512;e+=256){
      int hh = e >> 4; int c4 = (e & 15)*4;
      float4 v = *(const float4*)(Wl + (size_t)hh*CDIM + k0 + c4);
      Ws[c4+0][hh]=v.x; Ws[c4+1][hh]=v.y; Ws[c4+2][hh]=v.z; Ws[c4+3][hh]=v.w;
    }
    __syncthreads();
    #pragma unroll 16
    for (int k=0;k<64;k++){
      float w = Ws[k][hCol];
      #pragma unroll
      for (int r=0;r<8;r++) acc[r] = fmaf(Xs[rBase+r][k], w, acc[r]);
    }
    __syncthreads();
  }
  #pragma unroll
  for (int r=0;r<8;r++)
    g_lr[(size_t)(row0+rBase+r)*NHEADS + hCol] = acc[r];
}

// ============================================================
// TTT scan: one block per (b,h). 128 sequential mini-batch steps.
// GEMM-lets on mma.sync tf32 tensor cores (validated R10/R11).
// ============================================================
__global__ __launch_bounds__(256) void ttt_scan(
  const int*   __restrict__ pid,
  const float* __restrict__ W1in, const float* __restrict__ b1in,
  const float* __restrict__ lrb,  const float* __restrict__ ltid,
  const float* __restrict__ lnw,  const float* __restrict__ lnb)
{
  int b = blockIdx.x >> 5;
  int h = blockIdx.x & 31;
  __shared__ float W1s[64][72];
  __shared__ float gr[16][72];
  __shared__ float xq[16][68], xk[16][68], xv[16][68], zz[16][68];
  __shared__ float attn[16][20], Smat[16][20];
  __shared__ float b1s[64], gam[64], bet[64];
  __shared__ float etalr[16], ce[16], tok[16];
  __shared__ float ctab[16][32], stab[16][32];
  int t = threadIdx.x;
  int w = t >> 5, lane = t & 31;
  int g = lane >> 2, cc = lane & 3;

  for (int e=t;e<4096;e+=256) W1s[e>>6][e&63] = W1in[(size_t)h*4096 + e];
  if (t<64){ b1s[t]=b1in[h*64+t]; gam[t]=lnw[h*64+t]; bet[t]=lnb[h*64+t]; }
  if (t<16) tok[t] = fmaxf(1.f/(float)(t+1) + ltid[t], 0.f);
  for (int e=t;e<512;e+=256){
    int p = e >> 5, pi = e & 31;
    float inv = exp2f(-13.287712379549449f * (float)(2*pi) * (1.f/64.f));
    float ang = (float)p * inv;
    ctab[p][pi] = cosf(ang); stab[p][pi] = sinf(ang);
  }
  float lrbias = lrb[h];
  __syncthreads();

  const size_t PL = (size_t)BL*CDIM;
  const float* XQp = g_xqkv;
  const float* XKp = g_xqkv + PL;
  const float* XVp = g_xqkv + 2*PL;

  for (int m=0;m<NMB;m++){
    int l0 = m*MBSZ;
    for (int p=t;p<512;p+=256){
      int i = p >> 5, pi = p & 31;
      size_t base = ((size_t)b*LSEQ + l0 + i)*CDIM + h*64 + 2*pi;
      int pos = pid[(size_t)b*LSEQ + l0 + i] & 15;
      float c = ctab[pos][pi], s = stab[pos][pi];
      float q0=XQp[base], q1=XQp[base+1];
      xq[i][2*pi]   = q0*c - q1*s;
      xq[i][2*pi+1] = q1*c + q0*s;
      float k0=XKp[base], k1=XKp[base+1];
      xk[i][2*pi]   = k0*c - k1*s;
      xk[i][2*pi+1] = k1*c + k0*s;
    }
    for (int e=t;e<512;e+=256){
      int i = e >> 5, d2 = (e & 31)*2;
      float2 v = *(const float2*)(XVp + ((size_t)b*LSEQ + l0 + i)*CDIM + h*64 + d2);
      xv[i][d2] = v.x; xv[i][d2+1] = v.y;
    }
    if (t<16){
      float x = g_lr[((size_t)b*LSEQ + l0 + t)*NHEADS + h] + lrbias;
      float e = (1.f/(1.f+expf(-x))) * (1.f/64.f);
      etalr[t]=e; ce[t]=tok[15]*e;
    }
    __syncthreads();
    {
      const int n0 = w*8;
      float d0 = b1s[n0+2*cc], d1 = b1s[n0+2*cc+1];
      float d2 = d0, d3 = d1;
      #pragma unroll
      for (int ks=0; ks<8; ks++){
        const int kk = ks*8;
        uint32_t a0 = tfu(xk[g  ][kk+cc  ]), a1 = tfu(xk[8+g][kk+cc  ]);
        uint32_t a2 = tfu(xk[g  ][kk+cc+4]), a3 = tfu(xk[8+g][kk+cc+4]);
        uint32_t b0 = tfu(W1s[kk+cc][n0+g]), b1f= tfu(W1s[kk+cc+4][n0+g]);
        mma_tf32(d0,d1,d2,d3, a0,a1,a2,a3, b0,b1f);
      }
      zz[g  ][n0+2*cc]=d0; zz[g  ][n0+2*cc+1]=d1;
      zz[8+g][n0+2*cc]=d2; zz[8+g][n0+2*cc+1]=d3;
      if (w < 2){
        const int na = w*8;
        float e0=0.f,e1=0.f,e2=0.f,e3=0.f;
        #pragma unroll
        for (int ks=0; ks<8; ks++){
          const int kk = ks*8;
          uint32_t a0 = tfu(xq[g  ][kk+cc  ]), a1 = tfu(xq[8+g][kk+cc  ]);
          uint32_t a2 = tfu(xq[g  ][kk+cc+4]), a3 = tfu(xq[8+g][kk+cc+4]);
          uint32_t b0 = tfu(xk[na+g][kk+cc ]), b1f= tfu(xk[na+g][kk+cc+4]);
          mma_tf32(e0,e1,e2,e3, a0,a1,a2,a3, b0,b1f);
        }
        attn[g  ][na+2*cc]=e0; attn[g  ][na+2*cc+1]=e1;
        attn[8+g][na+2*cc]=e2; attn[8+g][na+2*cc+1]=e3;
      }
    }
    __syncthreads();
    {
      int i = t >> 4, j = t & 15;
      Smat[i][j] = (j <= i) ? -tok[i]*etalr[j]*(attn[i][j] + 1.f) : 0.f;
    }
    {
      for (int i=w;i<16;i+=8){
        float v0 = zz[i][lane], v1 = zz[i][lane+32];
        float sm = v0+v1, sq = v0*v0+v1*v1;
        #pragma unroll
        for (int o=16;o;o>>=1){ sm += __shfl_xor_sync(~0u, sm, o); sq += __shfl_xor_sync(~0u, sq, o); }
        float mu = sm * (1.f/64.f);
        float var = sq * (1.f/64.f) - mu*mu;
        float rstd = rsqrtf(var + EPSV);
        float xh0 = (v0-mu)*rstd, xh1 = (v1-mu)*rstd;
        float g0 = gam[lane], g1 = gam[lane+32];
        float y0 = g0*xh0 + bet[lane], y1 = g1*xh1 + bet[lane+32];
        float tg0 = (y0 - (xv[i][lane]    - xk[i][lane]   )) * g0;
        float tg1 = (y1 - (xv[i][lane+32] - xk[i][lane+32])) * g1;
        float sg = tg0+tg1, sgx = tg0*xh0 + tg1*xh1;
        #pragma unroll
        for (int o=16;o;o>>=1){ sg += __shfl_xor_sync(~0u, sg, o); sgx += __shfl_xor_sync(~0u, sgx, o); }
        float sc = rstd * (1.f/64.f);
        gr[i][lane]    = (64.f*tg0 - sg - xh0*sgx) * sc;
        gr[i][lane+32] = (64.f*tg1 - sg - xh1*sgx) * sc;
      }
    }
    __syncthreads();
    {
      const int n0 = w*8;
      float d0 = b1s[n0+2*cc], d1 = b1s[n0+2*cc+1];
      float d2 = d0, d3 = d1;
      #pragma unroll
      for (int ks=0; ks<8; ks++){
        const int kk = ks*8;
        uint32_t a0 = tfu(xq[g  ][kk+cc  ]), a1 = tfu(xq[8+g][kk+cc  ]);
        uint32_t a2 = tfu(xq[g  ][kk+cc+4]), a3 = tfu(xq[8+g][kk+cc+4]);
        uint32_t b0 = tfu(W1s[kk+cc][n0+g]), b1f= tfu(W1s[kk+cc+4][n0+g]);
        mma_tf32(d0,d1,d2,d3, a0,a1,a2,a3, b0,b1f);
      }
      #pragma unroll
      for (int ks=0; ks<2; ks++){
        const int kk = ks*8;
        uint32_t a0 = tfu(Smat[g  ][kk+cc  ]), a1 = tfu(Smat[8+g][kk+cc  ]);
        uint32_t a2 = tfu(Smat[g  ][kk+cc+4]), a3 = tfu(Smat[8+g][kk+cc+4]);
        uint32_t b0 = tfu(gr[kk+cc][n0+g]),   b1f= tfu(gr[kk+cc+4][n0+g]);
        mma_tf32(d0,d1,d2,d3, a0,a1,a2,a3, b0,b1f);
      }
      zz[g  ][n0+2*cc]=d0; zz[g  ][n0+2*cc+1]=d1;
      zz[8+g][n0+2*cc]=d2; zz[8+g][n0+2*cc+1]=d3;
    }
    __syncthreads();
    {
      for (int i=w;i<16;i+=8){
        float v0 = zz[i][lane], v1 = zz[i][lane+32];
        float sm = v0+v1, sq = v0*v0+v1*v1;
        #pragma unroll
        for (int o=16;o;o>>=1){ sm += __shfl_xor_sync(~0u, sm, o); sq += __shfl_xor_sync(~0u, sq, o); }
        float mu = sm*(1.f/64.f);
        float rstd = rsqrtf(sq*(1.f/64.f) - mu*mu + EPSV);
        size_t orow = ((size_t)b*LSEQ + l0 + i)*CDIM + h*64;
        g_Y[orow+lane]    = xq[i][lane]    + gam[lane]   *((v0-mu)*rstd) + bet[lane];
        g_Y[orow+lane+32] = xq[i][lane+32] + gam[lane+32]*((v1-mu)*rstd) + bet[lane+32];
      }
      const int m0 = 16*(w & 3);
      uint32_t ua[2][4];
      #pragma unroll
      for (int ks=0; ks<2; ks++){
        const int kk = ks*8;
        ua[ks][0] = tfu(-ce[kk+cc  ] * xk[kk+cc  ][m0+g  ]);
        ua[ks][1] = tfu(-ce[kk+cc  ] * xk[kk+cc  ][m0+8+g]);
        ua[ks][2] = tfu(-ce[kk+cc+4] * xk[kk+cc+4][m0+g  ]);
        ua[ks][3] = tfu(-ce[kk+cc+4] * xk[kk+cc+4][m0+8+g]);
      }
      #pragma unroll
      for (int nt=0; nt<4; nt++){
        const int nu = 32*(w>>2) + 8*nt;
        float d0 = W1s[m0+g  ][nu+2*cc], d1 = W1s[m0+g  ][nu+2*cc+1];
        float d2 = W1s[m0+8+g][nu+2*cc], d3 = W1s[m0+8+g][nu+2*cc+1];
        #pragma unroll
        for (int ks=0; ks<2; ks++){
          const int kk = ks*8;
          uint32_t b0 = tfu(gr[kk+cc][nu+g]), b1f = tfu(gr[kk+cc+4][nu+g]);
          mma_tf32(d0,d1,d2,d3, ua[ks][0],ua[ks][1],ua[ks][2],ua[ks][3], b0,b1f);
        }
        W1s[m0+g  ][nu+2*cc]=d0; W1s[m0+g  ][nu+2*cc+1]=d1;
        W1s[m0+8+g][nu+2*cc]=d2; W1s[m0+8+g][nu+2*cc+1]=d3;
      }
      if (t<64){
        float a = b1s[t];
        #pragma unroll
        for (int j=0;j<16;j++) a = fmaf(-ce[j], gr[j][t], a);
        b1s[t] = a;
      }
    }
    __syncthreads();
  }
}

// ============================================================
// Post layernorm over C=2048 per row -> split bf16 for out-GEMM
// ============================================================
__global__ __launch_bounds__(256) void rownorm(
    const float* __restrict__ w, const float* __restrict__ bias)
{
  int row = blockIdx.x; int t = threadIdx.x;
  const float* rp = g_Y + (size_t)row * CDIM;
  float s=0.f, ss=0.f;
  for (int c=t;c<CDIM;c+=256){ float v = rp[c]; s+=v; ss=fmaf(v,v,ss); }
  #pragma unroll
  for (int o=16;o;o>>=1){ s += __shfl_xor_sync(~0u,s,o); ss += __shfl_xor_sync(~0u,ss,o); }
  __shared__ float sw[8], ssw[8];
  int wid=t>>5, lane=t&31;
  if (lane==0){ sw[wid]=s; ssw[wid]=ss; }
  __syncthreads();
  float ts=0.f, tss=0.f;
  #pragma unroll
  for (int i2=0;i2<8;i2++){ ts+=sw[i2]; tss+=ssw[i2]; }
  float mu = ts*(1.f/CDIM);
  float rstd = rsqrtf(tss*(1.f/CDIM) - mu*mu + EPSV);
  __nv_bfloat16* op = g_Ys + (size_t)row*(2*CDIM);
  for (int c=t;c<CDIM;c+=256){
    float y = (rp[c]-mu)*rstd*w[c] + bias[c];
    __nv_bfloat16 hi = __float2bfloat16(y);
    size_t base = (size_t)(c>>5)*64 + (c&31);
    op[base]      = hi;
    op[base + 32] = __float2bfloat16(y - __bfloat162float(hi));
  }
}

// ============================================================
extern "C" void kernel_launch(void* const* d_in, const int* in_sizes, int n_in,
                              void* d_out, int out_size)
{
  const float* H   = (const float*)d_in[0];
  const int*   pid = (const int*)  d_in[1];
  const float* Wq  = (const float*)d_in[2];
  const float* Wk  = (const float*)d_in[3];
  const float* Wv  = (const float*)d_in[4];
  const float* Wo  = (const float*)d_in[5];
  const float* W1  = (const float*)d_in[6];
  const float* b1  = (const float*)d_in[7];
  const float* lrw = (const float*)d_in[8];
  const float* lrb = (const float*)d_in[9];
  const float* lti = (const float*)d_in[10];
  const float* lnw = (const float*)d_in[11];
  const float* lnb = (const float*)d_in[12];
  const float* pnw = (const float*)d_in[13];
  const float* pnb = (const float*)d_in[14];
  float* out = (float*)d_out;
  (void)in_sizes; (void)n_in; (void)out_size;

  static bool attr_set = false;
  if (!attr_set){
    cudaFuncSetAttribute(gemm_qkv_bf16, cudaFuncAttributeMaxDynamicSharedMemorySize, SM_GTOT);
    cudaFuncSetAttribute(gemm_out_bf16, cudaFuncAttributeMaxDynamicSharedMemorySize, SM_GTOT);
    attr_set = true;
  }

  __nv_bfloat16* wts = nullptr; cudaGetSymbolAddress((void**)&wts, g_wts);
  __nv_bfloat16* wos = nullptr; cudaGetSymbolAddress((void**)&wos, g_wos);

  transpose_split<<<dim3(64,64), 256>>>(Wq, wts,                            CDIM, CDIM);
  transpose_split<<<dim3(64,64), 256>>>(Wk, wts + (size_t)CDIM*2*CDIM,      CDIM, CDIM);
  transpose_split<<<dim3(64,64), 256>>>(Wv, wts + (size_t)2*CDIM*2*CDIM,    CDIM, CDIM);
  transpose_split<<<dim3(24,64), 256>>>(Wo, wos,                            CDIM, ODIM);
  split_H<<<(BL*(size_t)CDIM)/(256*4), 256>>>(H);

  gemm_qkv_bf16<<<dim3(24, BL/128), 256, SM_GTOT>>>();
  lr_gemm<<<BL/64, 256>>>(H, lrw);
  ttt_scan<<<BDIM*NHEADS, 256>>>(pid, W1, b1, lrb, lti, lnw, lnb);
  rownorm<<<BL, 256>>>(pnw, pnb);
  gemm_out_bf16<<<dim3(ODIM/256, BL/128), 256, SM_GTOT>>>(out);
}

// round 14
// speedup vs baseline: 1.1556x; 1.1314x over previous
#include <cuda_runtime.h>
#include <cuda_bf16.h>
#include <cstdint>
#include <cstddef>

#define NHEADS 32
#define HDIM 64
#define MBSZ 16
#define BDIM 4
#define LSEQ 2048
#define CDIM 2048
#define ODIM 768
#define NMB (LSEQ/MBSZ)
#define BL (BDIM*LSEQ)
#define EPSV 1e-6f

// -------- scratch (device globals; no allocations allowed) --------
__device__ float g_xqkv[(size_t)3*BL*CDIM];  // XQ | XK | XV, each [BL, C]
__device__ float g_lr[(size_t)BL*NHEADS];    // lr dot per (token, head)
__device__ float g_Y[(size_t)BL*CDIM];       // scan output, [B,L,C]
__device__ float g_YN[(size_t)BL*CDIM];      // post-norm output (tf32-rounded)
__device__ float g_Ht[(size_t)BL*CDIM];      // H rounded to tf32
__device__ float g_wt[(size_t)3*CDIM*CDIM];  // Wq^T | Wk^T | Wv^T  [N][K], tf32-rounded
__device__ float g_wot[(size_t)ODIM*CDIM];   // Wo^T [768][2048], tf32-rounded

// ============================================================
// helpers
// ============================================================
__device__ __forceinline__ float totf32(float x){
  uint32_t u; asm("cvt.rna.tf32.f32 %0, %1;" : "=r"(u) : "f"(x));
  return __uint_as_float(u);
}
__device__ __forceinline__ uint32_t tfu(float x){
  uint32_t u; asm("cvt.rna.tf32.f32 %0, %1;" : "=r"(u) : "f"(x));
  return u;
}
__device__ __forceinline__ void mma_tf32(float& d0, float& d1, float& d2, float& d3,
                                         uint32_t a0, uint32_t a1, uint32_t a2, uint32_t a3,
                                         uint32_t b0, uint32_t b1){
  asm volatile(
    "mma.sync.aligned.m16n8k8.row.col.f32.tf32.tf32.f32 "
    "{%0,%1,%2,%3}, {%4,%5,%6,%7}, {%8,%9}, {%0,%1,%2,%3};"
    : "+f"(d0), "+f"(d1), "+f"(d2), "+f"(d3)
    : "r"(a0), "r"(a1), "r"(a2), "r"(a3), "r"(b0), "r"(b1));
}
__device__ __forceinline__ void ldm4(uint32_t& r0, uint32_t& r1, uint32_t& r2, uint32_t& r3,
                                     uint32_t addr){
  asm volatile("ldmatrix.sync.aligned.m8n8.x4.shared.b16 {%0,%1,%2,%3}, [%4];"
    : "=r"(r0), "=r"(r1), "=r"(r2), "=r"(r3) : "r"(addr));
}
__device__ __forceinline__ uint32_t smem_u32(const void* p){
  uint32_t a;
  asm("{ .reg .u64 t; cvta.to.shared.u64 t, %1; cvt.u32.u64 %0, t; }" : "=r"(a) : "l"(p));
  return a;
}
__device__ __forceinline__ void cpa16(uint32_t dst, const void* src){
  asm volatile("cp.async.cg.shared.global [%0], [%1], 16;" :: "r"(dst), "l"(src));
}
__device__ __forceinline__ void cpa_commit(){
  asm volatile("cp.async.commit_group;" ::: "memory");
}

// SMEM tile: rows of 32 tf32 = 128B padded to 144B; A 128 rows + B 256 rows contiguous
#define A_ST_B (128*144)
#define STG_B  ((128+256)*144)          // 55296
#define NSTG 3
#define SM_GTOT (NSTG*STG_B)            // 165888

// ============================================================
// tf32 GEMM: C[M,Ntot] = A[M,2048] @ Bt[Ntot,2048]^T
// CTA tile 128x256, 512 threads (16 warps: 4m x 4n), warp tile 32x64
// fragments via ldmatrix (b16 x4 trick for tf32); 3-stage cp.async
// ============================================================
__device__ __forceinline__ void gemm_tf32_body(
    const float* __restrict__ A, const float* __restrict__ Bt,
    float* __restrict__ C, int Ntot, int n0, int cRow)
{
  extern __shared__ float smem[];
  const uint32_t sb = smem_u32(smem);

  const int t    = threadIdx.x;
  const int wid  = t >> 5, lane = t & 31;
  const int wm   = wid & 3;        // 0..3 -> 32-row slab
  const int wn   = wid >> 2;       // 0..3 -> 64-col slab
  const int g    = lane >> 2;
  const int cc   = lane & 3;

  // ldmatrix lane-address patterns (tf32-as-2xb16 mats)
  const uint32_t aoff = (uint32_t)(wm*32 + (lane & 15))*144 + (uint32_t)(lane >> 4)*16;
  const uint32_t boff = (uint32_t)A_ST_B + (uint32_t)(wn*64 + (lane & 15))*144 + (uint32_t)(lane >> 4)*16;

  float d[2][8][4];
  #pragma unroll
  for (int mi=0;mi<2;mi++)
    #pragma unroll
    for (int ni=0;ni<8;ni++)
      #pragma unroll
      for (int r=0;r<4;r++) d[mi][ni][r]=0.f;

  auto issue = [&](int c2, int buf){
    const uint32_t st = sb + buf*STG_B;
    #pragma unroll
    for (int it=0; it<6; it++){
      int e = it*512 + t;
      int row = e >> 3, u = e & 7;
      const float* src = (row < 128)
        ? A  + (size_t)(cRow+row)*CDIM     + c2*32 + u*4
        : Bt + (size_t)(n0+row-128)*CDIM   + c2*32 + u*4;
      cpa16(st + (uint32_t)row*144 + (uint32_t)u*16, src);
    }
    cpa_commit();
  };

  issue(0, 0);
  issue(1, 1);

  for (int c=0; c<64; c++){
    if (c==63) asm volatile("cp.async.wait_group 0;" ::: "memory");
    else       asm volatile("cp.async.wait_group 1;" ::: "memory");
    __syncthreads();
    if (c+2 < 64) issue(c+2, (c+2)%NSTG);

    const uint32_t stb = sb + (c%NSTG)*STG_B;
    #pragma unroll
    for (int ks=0; ks<4; ks++){
      uint32_t a0[4], a1[4];
      ldm4(a0[0],a0[1],a0[2],a0[3], stb + aoff +        ks*32);
      ldm4(a1[0],a1[1],a1[2],a1[3], stb + aoff + 2304 + ks*32);   // +16 rows
      #pragma unroll
      for (int pr=0; pr<4; pr++){
        uint32_t b0,b1,b2,b3;
        ldm4(b0,b1,b2,b3, stb + boff + pr*2304 + ks*32);
        // b0/b2 = cols of n-tile 2pr ; b1/b3 = n-tile 2pr+1
        mma_tf32(d[0][2*pr  ][0], d[0][2*pr  ][1], d[0][2*pr  ][2], d[0][2*pr  ][3],
                 a0[0],a0[1],a0[2],a0[3], b0, b2);
        mma_tf32(d[1][2*pr  ][0], d[1][2*pr  ][1], d[1][2*pr  ][2], d[1][2*pr  ][3],
                 a1[0],a1[1],a1[2],a1[3], b0, b2);
        mma_tf32(d[0][2*pr+1][0], d[0][2*pr+1][1], d[0][2*pr+1][2], d[0][2*pr+1][3],
                 a0[0],a0[1],a0[2],a0[3], b1, b3);
        mma_tf32(d[1][2*pr+1][0], d[1][2*pr+1][1], d[1][2*pr+1][2], d[1][2*pr+1][3],
                 a1[0],a1[1],a1[2],a1[3], b1, b3);
      }
    }
  }

  #pragma unroll
  for (int mi=0; mi<2; mi++){
    int row = cRow + wm*32 + mi*16 + g;
    #pragma unroll
    for (int ni=0; ni<8; ni++){
      int col = n0 + wn*64 + ni*8 + cc*2;
      *(float2*)(C + (size_t)row*Ntot + col) =
          make_float2(d[mi][ni][0], d[mi][ni][1]);
      *(float2*)(C + (size_t)(row+8)*Ntot + col) =
          make_float2(d[mi][ni][2], d[mi][ni][3]);
    }
  }
}

__global__ __launch_bounds__(512,1) void gemm_qkv_tf32(){
  const int z = blockIdx.x >> 3;
  const int n = blockIdx.x & 7;
  const float* Bt = g_wt + (size_t)z * CDIM * CDIM;
  float* Cc = g_xqkv + (size_t)z * (size_t)BL * CDIM;
  gemm_tf32_body(g_Ht, Bt, Cc, CDIM, n*256, blockIdx.y*128);
}
__global__ __launch_bounds__(512,1) void gemm_out_tf32(float* __restrict__ out){
  gemm_tf32_body(g_YN, g_wot, out, ODIM, blockIdx.x*256, blockIdx.y*128);
}

// ============================================================
// prep: transpose + tf32 round; round-copy H
// ============================================================
__global__ __launch_bounds__(256) void transpose_k(
    const float* __restrict__ in, float* __restrict__ out, int R, int C)
{
  __shared__ float tile[32][33];
  int c0 = blockIdx.x*32, r0 = blockIdx.y*32;
  int tx = threadIdx.x & 31, ty = threadIdx.x >> 5;
  for (int i=ty; i<32; i+=8) tile[i][tx] = in[(size_t)(r0+i)*C + c0 + tx];
  __syncthreads();
  for (int i=ty; i<32; i+=8) out[(size_t)(c0+i)*R + r0 + tx] = totf32(tile[tx][i]);
}

__global__ __launch_bounds__(256) void round_tf32(const float* __restrict__ in){
  size_t i = ((size_t)blockIdx.x*256 + threadIdx.x)*4;
  float4 v = *(const float4*)(in + i);
  v.x=totf32(v.x); v.y=totf32(v.y); v.z=totf32(v.z); v.w=totf32(v.w);
  *(float4*)(g_Ht + i) = v;
}

// ============================================================
// lr dot: out[row, h] = sum_c X[row,c] * lrw[h,c]
// ============================================================
__global__ __launch_bounds__(256) void lr_gemm(
    const float* __restrict__ X, const float* __restrict__ Wl)
{
  __shared__ float Xs[64][65];
  __shared__ float Ws[64][33];
  int t = threadIdx.x;
  int row0 = blockIdx.x * 64;
  float acc[8];
  #pragma unroll
  for (int r=0;r<8;r++) acc[r]=0.f;
  int rBase = (t >> 5) * 8;
  int hCol  = t & 31;
  for (int k0=0;k0<CDIM;k0+=64){
    for (int e=t;e<1024;e+=256){
      int r = e >> 4; int c4 = (e & 15)*4;
      float4 v = *(const float4*)(X + (size_t)(row0+r)*CDIM + k0 + c4);
      Xs[r][c4+0]=v.x; Xs[r][c4+1]=v.y; Xs[r][c4+2]=v.z; Xs[r][c4+3]=v.w;
    }
    for (int e=t;e<512;e+=256){
      int hh = e >> 4; int c4 = (e & 15)*4;
      float4 v = *(const float4*)(Wl + (size_t)hh*CDIM + k0 + c4);
      Ws[c4+0][hh]=v.x; Ws[c4+1][hh]=v.y; Ws[c4+2][hh]=v.z; Ws[c4+3][hh]=v.w;
    }
    __syncthreads();
    #pragma unroll 16
    for (int k=0;k<64;k++){
      float w = Ws[k][hCol];
      #pragma unroll
      for (int r=0;r<8;r++) acc[r] = fmaf(Xs[rBase+r][k], w, acc[r]);
    }
    __syncthreads();
  }
  #pragma unroll
  for (int r=0;r<8;r++)
    g_lr[(size_t)(row0+rBase+r)*NHEADS + hCol] = acc[r];
}

// ============================================================
// TTT scan: one block per (b,h), 256 threads, 128 sequential steps.
// W1 master lives in registers (phase-E fragment layout); each step
// re-emits Wh/Wl (2-term tf32 split) to SMEM for Z1/Z1bar mmas.
// Dynamic SMEM layout (floats):
//  Whs[64][72] @0, Wls[64][72] @4608, gr[16][72] @9216,
//  xq[16][68] @10368, xk @11456, xv @12544, zz @13632,
//  attn[16][20] @14720, Smat @15040, b1s @15360, gam @15424, bet @15488,
//  etalr @15552, ce @15568, tok @15584, ctab[512] @15600, stab @16112. end 16624.
// ============================================================
#define SCAN_SM (16624*4)

__global__ __launch_bounds__(256) void ttt_scan(
  const int*   __restrict__ pid,
  const float* __restrict__ W1in, const float* __restrict__ b1in,
  const float* __restrict__ lrb,  const float* __restrict__ ltid,
  const float* __restrict__ lnw,  const float* __restrict__ lnb)
{
  extern __shared__ float sm[];
  float (*Whs)[72] = (float(*)[72])(sm);
  float (*Wls)[72] = (float(*)[72])(sm + 4608);
  float (*gr )[72] = (float(*)[72])(sm + 9216);
  float (*xq )[68] = (float(*)[68])(sm + 10368);
  float (*xk )[68] = (float(*)[68])(sm + 11456);
  float (*xv )[68] = (float(*)[68])(sm + 12544);
  float (*zz )[68] = (float(*)[68])(sm + 13632);
  float (*attn)[20] = (float(*)[20])(sm + 14720);
  float (*Smat)[20] = (float(*)[20])(sm + 15040);
  float* b1s = sm + 15360;
  float* gam = sm + 15424;
  float* bet = sm + 15488;
  float* etalr = sm + 15552;
  float* ce  = sm + 15568;
  float* tok = sm + 15584;
  float (*ctab)[32] = (float(*)[32])(sm + 15600);
  float (*stab)[32] = (float(*)[32])(sm + 16112);

  int b = blockIdx.x >> 5;
  int h = blockIdx.x & 31;
  int t = threadIdx.x;
  int w = t >> 5, lane = t & 31;
  int g = lane >> 2, cc = lane & 3;

  // W1 master in registers, phase-E fragment layout
  const int m0 = 16*(w & 3);
  const int nbase = 32*(w >> 2);
  float accw[4][4];
  #pragma unroll
  for (int nt=0; nt<4; nt++){
    int nu = nbase + 8*nt;
    accw[nt][0] = W1in[(size_t)h*4096 + (m0+g  )*64 + nu+2*cc  ];
    accw[nt][1] = W1in[(size_t)h*4096 + (m0+g  )*64 + nu+2*cc+1];
    accw[nt][2] = W1in[(size_t)h*4096 + (m0+8+g)*64 + nu+2*cc  ];
    accw[nt][3] = W1in[(size_t)h*4096 + (m0+8+g)*64 + nu+2*cc+1];
  }
  if (t<64){ b1s[t]=b1in[h*64+t]; gam[t]=lnw[h*64+t]; bet[t]=lnb[h*64+t]; }
  if (t<16) tok[t] = fmaxf(1.f/(float)(t+1) + ltid[t], 0.f);
  for (int e=t;e<512;e+=256){
    int p = e >> 5, pi = e & 31;
    float inv = exp2f(-13.287712379549449f * (float)(2*pi) * (1.f/64.f));
    float ang = (float)p * inv;
    ctab[p][pi] = cosf(ang); stab[p][pi] = sinf(ang);
  }
  float lrbias = lrb[h];
  __syncthreads();

  const size_t PL = (size_t)BL*CDIM;
  const float* XQp = g_xqkv;
  const float* XKp = g_xqkv + PL;
  const float* XVp = g_xqkv + 2*PL;

  for (int m=0;m<NMB;m++){
    int l0 = m*MBSZ;
    // ---------- phase A: emit Wh/Wl from master; load tiles + RoPE ----------
    #pragma unroll
    for (int nt=0; nt<4; nt++){
      int nu = nbase + 8*nt;
      #pragma unroll
      for (int j=0;j<4;j++){
        int rr = m0 + ((j & 2) ? 8+g : g);
        int ccol = nu + 2*cc + (j & 1);
        float v = accw[nt][j];
        float hf = __uint_as_float(tfu(v));
        Whs[rr][ccol] = hf;
        Wls[rr][ccol] = __uint_as_float(tfu(v - hf));
      }
    }
    for (int p=t;p<512;p+=256){
      int i = p >> 5, pi = p & 31;
      size_t base = ((size_t)b*LSEQ + l0 + i)*CDIM + h*64 + 2*pi;
      int pos = pid[(size_t)b*LSEQ + l0 + i] & 15;
      float c = ctab[pos][pi], s = stab[pos][pi];
      float q0=XQp[base], q1=XQp[base+1];
      xq[i][2*pi]   = q0*c - q1*s;
      xq[i][2*pi+1] = q1*c + q0*s;
      float k0=XKp[base], k1=XKp[base+1];
      xk[i][2*pi]   = k0*c - k1*s;
      xk[i][2*pi+1] = k1*c + k0*s;
    }
    for (int e=t;e<512;e+=256){
      int i = e >> 5, d2 = (e & 31)*2;
      float2 v = *(const float2*)(XVp + ((size_t)b*LSEQ + l0 + i)*CDIM + h*64 + d2);
      xv[i][d2] = v.x; xv[i][d2+1] = v.y;
    }
    if (t<16){
      float x = g_lr[((size_t)b*LSEQ + l0 + t)*NHEADS + h] + lrbias;
      float e = (1.f/(1.f+expf(-x))) * (1.f/64.f);
      etalr[t]=e; ce[t]=tok[15]*e;
    }
    __syncthreads();
    // ---------- phase B: Z1 = xk@(Wh+Wl) + b1 ; attn = xq@xk^T (warps 0-1) ----------
    {
      const int n0 = w*8;
      float d0 = b1s[n0+2*cc], d1 = b1s[n0+2*cc+1];
      float d2 = d0, d3 = d1;
      #pragma unroll
      for (int ks=0; ks<8; ks++){
        const int kk = ks*8;
        uint32_t a0 = tfu(xk[g  ][kk+cc  ]), a1 = tfu(xk[8+g][kk+cc  ]);
        uint32_t a2 = tfu(xk[g  ][kk+cc+4]), a3 = tfu(xk[8+g][kk+cc+4]);
        uint32_t bh0 = __float_as_uint(Whs[kk+cc][n0+g]);
        uint32_t bh1 = __float_as_uint(Whs[kk+cc+4][n0+g]);
        uint32_t bl0 = __float_as_uint(Wls[kk+cc][n0+g]);
        uint32_t bl1 = __float_as_uint(Wls[kk+cc+4][n0+g]);
        mma_tf32(d0,d1,d2,d3, a0,a1,a2,a3, bh0,bh1);
        mma_tf32(d0,d1,d2,d3, a0,a1,a2,a3, bl0,bl1);
      }
      zz[g  ][n0+2*cc]=d0; zz[g  ][n0+2*cc+1]=d1;
      zz[8+g][n0+2*cc]=d2; zz[8+g][n0+2*cc+1]=d3;
      if (w < 2){
        const int na = w*8;
        float e0=0.f,e1=0.f,e2=0.f,e3=0.f;
        #pragma unroll
        for (int ks=0; ks<8; ks++){
          const int kk = ks*8;
          uint32_t a0 = tfu(xq[g  ][kk+cc  ]), a1 = tfu(xq[8+g][kk+cc  ]);
          uint32_t a2 = tfu(xq[g  ][kk+cc+4]), a3 = tfu(xq[8+g][kk+cc+4]);
          uint32_t b0 = tfu(xk[na+g][kk+cc ]), b1f= tfu(xk[na+g][kk+cc+4]);
          mma_tf32(e0,e1,e2,e3, a0,a1,a2,a3, b0,b1f);
        }
        attn[g  ][na+2*cc]=e0; attn[g  ][na+2*cc+1]=e1;
        attn[8+g][na+2*cc]=e2; attn[8+g][na+2*cc+1]=e3;
      }
    }
    __syncthreads();
    // ---------- phase C: build S; grad = LN fused L2 bwd ----------
    {
      int i = t >> 4, j = t & 15;
      Smat[i][j] = (j <= i) ? -tok[i]*etalr[j]*(attn[i][j] + 1.f) : 0.f;
    }
    {
      for (int i=w;i<16;i+=8){
        float v0 = zz[i][lane], v1 = zz[i][lane+32];
        float sm2 = v0+v1, sq = v0*v0+v1*v1;
        #pragma unroll
        for (int o=16;o;o>>=1){ sm2 += __shfl_xor_sync(~0u, sm2, o); sq += __shfl_xor_sync(~0u, sq, o); }
        float mu = sm2 * (1.f/64.f);
        float var = sq * (1.f/64.f) - mu*mu;
        float rstd = rsqrtf(var + EPSV);
        float xh0 = (v0-mu)*rstd, xh1 = (v1-mu)*rstd;
        float g0 = gam[lane], g1 = gam[lane+32];
        float y0 = g0*xh0 + bet[lane], y1 = g1*xh1 + bet[lane+32];
        float tg0 = (y0 - (xv[i][lane]    - xk[i][lane]   )) * g0;
        float tg1 = (y1 - (xv[i][lane+32] - xk[i][lane+32])) * g1;
        float sg = tg0+tg1, sgx = tg0*xh0 + tg1*xh1;
        #pragma unroll
        for (int o=16;o;o>>=1){ sg += __shfl_xor_sync(~0u, sg, o); sgx += __shfl_xor_sync(~0u, sgx, o); }
        float sc = rstd * (1.f/64.f);
        gr[i][lane]    = (64.f*tg0 - sg - xh0*sgx) * sc;
        gr[i][lane+32] = (64.f*tg1 - sg - xh1*sgx) * sc;
      }
    }
    __syncthreads();
    // ---------- phase D: Z1bar = xq@(Wh+Wl) + b1 + (-S)@gr ----------
    {
      const int n0 = w*8;
      float d0 = b1s[n0+2*cc], d1 = b1s[n0+2*cc+1];
      float d2 = d0, d3 = d1;
      #pragma unroll
      for (int ks=0; ks<8; ks++){
        const int kk = ks*8;
        uint32_t a0 = tfu(xq[g  ][kk+cc  ]), a1 = tfu(xq[8+g][kk+cc  ]);
        uint32_t a2 = tfu(xq[g  ][kk+cc+4]), a3 = tfu(xq[8+g][kk+cc+4]);
        uint32_t bh0 = __float_as_uint(Whs[kk+cc][n0+g]);
        uint32_t bh1 = __float_as_uint(Whs[kk+cc+4][n0+g]);
        uint32_t bl0 = __float_as_uint(Wls[kk+cc][n0+g]);
        uint32_t bl1 = __float_as_uint(Wls[kk+cc+4][n0+g]);
        mma_tf32(d0,d1,d2,d3, a0,a1,a2,a3, bh0,bh1);
        mma_tf32(d0,d1,d2,d3, a0,a1,a2,a3, bl0,bl1);
      }
      #pragma unroll
      for (int ks=0; ks<2; ks++){
        const int kk = ks*8;
        uint32_t a0 = tfu(Smat[g  ][kk+cc  ]), a1 = tfu(Smat[8+g][kk+cc  ]);
        uint32_t a2 = tfu(Smat[g  ][kk+cc+4]), a3 = tfu(Smat[8+g][kk+cc+4]);
        uint32_t b0 = tfu(gr[kk+cc][n0+g]),   b1f= tfu(gr[kk+cc+4][n0+g]);
        mma_tf32(d0,d1,d2,d3, a0,a1,a2,a3, b0,b1f);
      }
      zz[g  ][n0+2*cc]=d0; zz[g  ][n0+2*cc+1]=d1;
      zz[8+g][n0+2*cc]=d2; zz[8+g][n0+2*cc+1]=d3;
    }
    __syncthreads();
    // ---------- phase E: out = xq + LN(Z1bar); W1 (registers) & b1 update ----------
    {
      for (int i=w;i<16;i+=8){
        float v0 = zz[i][lane], v1 = zz[i][lane+32];
        float sm2 = v0+v1, sq = v0*v0+v1*v1;
        #pragma unroll
        for (int o=16;o;o>>=1){ sm2 += __shfl_xor_sync(~0u, sm2, o); sq += __shfl_xor_sync(~0u, sq, o); }
        float mu = sm2*(1.f/64.f);
        float rstd = rsqrtf(sq*(1.f/64.f) - mu*mu + EPSV);
        size_t orow = ((size_t)b*LSEQ + l0 + i)*CDIM + h*64;
        g_Y[orow+lane]    = xq[i][lane]    + gam[lane]   *((v0-mu)*rstd) + bet[lane];
        g_Y[orow+lane+32] = xq[i][lane+32] + gam[lane+32]*((v1-mu)*rstd) + bet[lane+32];
      }
      // W1 -= (ce*xk)^T @ gr  : registers d = (-A)@B + accw
      uint32_t ua[2][4];
      #pragma unroll
      for (int ks=0; ks<2; ks++){
        const int kk = ks*8;
        ua[ks][0] = tfu(-ce[kk+cc  ] * xk[kk+cc  ][m0+g  ]);
        ua[ks][1] = tfu(-ce[kk+cc  ] * xk[kk+cc  ][m0+8+g]);
        ua[ks][2] = tfu(-ce[kk+cc+4] * xk[kk+cc+4][m0+g  ]);
        ua[ks][3] = tfu(-ce[kk+cc+4] * xk[kk+cc+4][m0+8+g]);
      }
      #pragma unroll
      for (int nt=0; nt<4; nt++){
        const int nu = nbase + 8*nt;
        #pragma unroll
        for (int ks=0; ks<2; ks++){
          const int kk = ks*8;
          uint32_t b0 = tfu(gr[kk+cc][nu+g]), b1f = tfu(gr[kk+cc+4][nu+g]);
          mma_tf32(accw[nt][0],accw[nt][1],accw[nt][2],accw[nt][3],
                   ua[ks][0],ua[ks][1],ua[ks][2],ua[ks][3], b0,b1f);
        }
      }
      if (t<64){
        float a = b1s[t];
        #pragma unroll
        for (int j=0;j<16;j++) a = fmaf(-ce[j], gr[j][t], a);
        b1s[t] = a;
      }
    }
    __syncthreads();
  }
}

// ============================================================
// Post layernorm over C=2048 per row (output tf32-rounded for out-GEMM)
// ============================================================
__global__ __launch_bounds__(256) void rownorm(
    const float* __restrict__ w, const float* __restrict__ bias)
{
  int row = blockIdx.x; int t = threadIdx.x;
  const float* rp = g_Y + (size_t)row * CDIM;
  float s=0.f, ss=0.f;
  for (int c=t;c<CDIM;c+=256){ float v = rp[c]; s+=v; ss=fmaf(v,v,ss); }
  #pragma unroll
  for (int o=16;o;o>>=1){ s += __shfl_xor_sync(~0u,s,o); ss += __shfl_xor_sync(~0u,ss,o); }
  __shared__ float sw[8], ssw[8];
  int wid=t>>5, lane=t&31;
  if (lane==0){ sw[wid]=s; ssw[wid]=ss; }
  __syncthreads();
  float ts=0.f, tss=0.f;
  #pragma unroll
  for (int i2=0;i2<8;i2++){ ts+=sw[i2]; tss+=ssw[i2]; }
  float mu = ts*(1.f/CDIM);
  float rstd = rsqrtf(tss*(1.f/CDIM) - mu*mu + EPSV);
  float* op = g_YN + (size_t)row*CDIM;
  for (int c=t;c<CDIM;c+=256){
    float v=rp[c];
    op[c] = totf32((v-mu)*rstd*w[c] + bias[c]);
  }
}

// ============================================================
extern "C" void kernel_launch(void* const* d_in, const int* in_sizes, int n_in,
                              void* d_out, int out_size)
{
  const float* H   = (const float*)d_in[0];
  const int*   pid = (const int*)  d_in[1];
  const float* Wq  = (const float*)d_in[2];
  const float* Wk  = (const float*)d_in[3];
  const float* Wv  = (const float*)d_in[4];
  const float* Wo  = (const float*)d_in[5];
  const float* W1  = (const float*)d_in[6];
  const float* b1  = (const float*)d_in[7];
  const float* lrw = (const float*)d_in[8];
  const float* lrb = (const float*)d_in[9];
  const float* lti = (const float*)d_in[10];
  const float* lnw = (const float*)d_in[11];
  const float* lnb = (const float*)d_in[12];
  const float* pnw = (const float*)d_in[13];
  const float* pnb = (const float*)d_in[14];
  float* out = (float*)d_out;
  (void)in_sizes; (void)n_in; (void)out_size;

  static bool attr_set = false;
  if (!attr_set){
    cudaFuncSetAttribute(gemm_qkv_tf32, cudaFuncAttributeMaxDynamicSharedMemorySize, SM_GTOT);
    cudaFuncSetAttribute(gemm_out_tf32, cudaFuncAttributeMaxDynamicSharedMemorySize, SM_GTOT);
    cudaFuncSetAttribute(ttt_scan,      cudaFuncAttributeMaxDynamicSharedMemorySize, SCAN_SM);
    attr_set = true;
  }

  float* wt0 = nullptr; cudaGetSymbolAddress((void**)&wt0, g_wt);
  float* wot = nullptr; cudaGetSymbolAddress((void**)&wot, g_wot);

  transpose_k<<<dim3(64,64), 256>>>(Wq, wt0,                         CDIM, CDIM);
  transpose_k<<<dim3(64,64), 256>>>(Wk, wt0 + (size_t)CDIM*CDIM,     CDIM, CDIM);
  transpose_k<<<dim3(64,64), 256>>>(Wv, wt0 + (size_t)2*CDIM*CDIM,   CDIM, CDIM);
  transpose_k<<<dim3(24,64), 256>>>(Wo, wot,                         CDIM, ODIM);
  round_tf32<<<(BL*(size_t)CDIM)/(256*4), 256>>>(H);

  gemm_qkv_tf32<<<dim3(24, BL/128), 512, SM_GTOT>>>();
  lr_gemm<<<BL/64, 256>>>(H, lrw);
  ttt_scan<<<BDIM*NHEADS, 256, SCAN_SM>>>(pid, W1, b1, lrb, lti, lnw, lnb);
  rownorm<<<BL, 256>>>(pnw, pnb);
  gemm_out_tf32<<<dim3(ODIM/256, BL/128), 512, SM_GTOT>>>(out);
}

// round 15
// speedup vs baseline: 1.7272x; 1.4946x over previous
#include <cuda_runtime.h>
#include <cuda_fp16.h>
#include <cstdint>
#include <cstddef>

#define NHEADS 32
#define HDIM 64
#define MBSZ 16
#define BDIM 4
#define LSEQ 2048
#define CDIM 2048
#define ODIM 768
#define NMB (LSEQ/MBSZ)
#define BL (BDIM*LSEQ)
#define EPSV 1e-6f

// -------- scratch (device globals; no allocations allowed) --------
__device__ float g_xqkv[(size_t)3*BL*CDIM];  // XQ | XK | XV, each [BL, C]
__device__ float g_lr[(size_t)BL*NHEADS];    // lr dot per (token, head)
__device__ float g_Y[(size_t)BL*CDIM];       // scan output, [B,L,C]
__device__ __half g_Hh[(size_t)BL*CDIM];     // H as fp16
__device__ __half g_wth[(size_t)3*CDIM*CDIM];// Wq^T|Wk^T|Wv^T fp16, [N][K]
__device__ __half g_woh[(size_t)ODIM*CDIM];  // Wo^T fp16
__device__ __half g_Yh[(size_t)BL*CDIM];     // post-norm fp16

// ============================================================
// helpers
// ============================================================
__device__ __forceinline__ uint32_t tfu(float x){
  uint32_t u; asm("cvt.rna.tf32.f32 %0, %1;" : "=r"(u) : "f"(x));
  return u;
}
__device__ __forceinline__ void mma_tf32(float& d0, float& d1, float& d2, float& d3,
                                         uint32_t a0, uint32_t a1, uint32_t a2, uint32_t a3,
                                         uint32_t b0, uint32_t b1){
  asm volatile(
    "mma.sync.aligned.m16n8k8.row.col.f32.tf32.tf32.f32 "
    "{%0,%1,%2,%3}, {%4,%5,%6,%7}, {%8,%9}, {%0,%1,%2,%3};"
    : "+f"(d0), "+f"(d1), "+f"(d2), "+f"(d3)
    : "r"(a0), "r"(a1), "r"(a2), "r"(a3), "r"(b0), "r"(b1));
}
__device__ __forceinline__ void mma_f16(float& d0, float& d1, float& d2, float& d3,
                                        uint32_t a0, uint32_t a1, uint32_t a2, uint32_t a3,
                                        uint32_t b0, uint32_t b1){
  asm volatile(
    "mma.sync.aligned.m16n8k16.row.col.f32.f16.f16.f32 "
    "{%0,%1,%2,%3}, {%4,%5,%6,%7}, {%8,%9}, {%0,%1,%2,%3};"
    : "+f"(d0), "+f"(d1), "+f"(d2), "+f"(d3)
    : "r"(a0), "r"(a1), "r"(a2), "r"(a3), "r"(b0), "r"(b1));
}
__device__ __forceinline__ void ldm4(uint32_t& r0, uint32_t& r1, uint32_t& r2, uint32_t& r3,
                                     uint32_t addr){
  asm volatile("ldmatrix.sync.aligned.m8n8.x4.shared.b16 {%0,%1,%2,%3}, [%4];"
    : "=r"(r0), "=r"(r1), "=r"(r2), "=r"(r3) : "r"(addr));
}
__device__ __forceinline__ uint32_t smem_u32(const void* p){
  uint32_t a;
  asm("{ .reg .u64 t; cvta.to.shared.u64 t, %1; cvt.u32.u64 %0, t; }" : "=r"(a) : "l"(p));
  return a;
}
__device__ __forceinline__ void cpa16(uint32_t dst, const void* src){
  asm volatile("cp.async.cg.shared.global [%0], [%1], 16;" :: "r"(dst), "l"(src));
}
__device__ __forceinline__ void cpa_commit(){
  asm volatile("cp.async.commit_group;" ::: "memory");
}

// SMEM tile: rows of 64 fp16 = 128B payload, padded to 144B
#define A_ST_B (128*144)
#define STG_B  ((128+256)*144)          // 55296
#define NSTG 3
#define SM_GTOT (NSTG*STG_B)            // 165888

// ============================================================
// fp16 GEMM: C[M,Ntot] = A[M,2048] @ Bt[Ntot,2048]^T (fp32 accum)
// CTA tile 128x256, 256 threads (8 warps: 2m x 4n), warp tile 64x64
// K-chunk 64; fragments via ldmatrix.b16; 3-stage cp.async pipeline
// ============================================================
__device__ __forceinline__ void gemm_f16_body(
    const __half* __restrict__ A, const __half* __restrict__ Bt,
    float* __restrict__ C, int Ntot, int n0, int cRow)
{
  extern __shared__ float smem[];
  const uint32_t sb = smem_u32(smem);

  const int t    = threadIdx.x;
  const int wid  = t >> 5, lane = t & 31;
  const int wm   = wid & 1;        // 0..1 -> 64-row slab
  const int wn   = wid >> 1;       // 0..3 -> 64-col slab
  const int g    = lane >> 2;
  const int cc   = lane & 3;

  const int ldrow = t >> 3;        // 0..31
  const int ld16  = t & 7;         // 16B unit within 128B payload

  // ldmatrix lane-address offsets
  // A x4 mats: (m0-7,k0-7)(m8-15,k0-7)(m0-7,k8-15)(m8-15,k8-15)
  const uint32_t aoff = (uint32_t)(wm*64 + (lane & 15))*144 + (uint32_t)(lane >> 4)*16;
  // B x4 mats: (n0-7,k0-7)(n0-7,k8-15)(n8-15,k0-7)(n8-15,k8-15)
  const uint32_t boff = (uint32_t)A_ST_B
      + (uint32_t)(wn*64 + ((lane & 16) ? 8 : 0) + (lane & 7))*144
      + (uint32_t)((lane & 8) ? 16 : 0);

  float d[4][8][4];
  #pragma unroll
  for (int mi=0;mi<4;mi++)
    #pragma unroll
    for (int ni=0;ni<8;ni++)
      #pragma unroll
      for (int r=0;r<4;r++) d[mi][ni][r]=0.f;

  auto issue = [&](int c2, int buf){
    const uint32_t st = sb + buf*STG_B;
    #pragma unroll
    for (int it=0; it<4; it++){
      int row = ldrow + it*32;
      cpa16(st + (uint32_t)row*144 + (uint32_t)ld16*16,
            A + (size_t)(cRow+row)*CDIM + c2*64 + ld16*8);
    }
    #pragma unroll
    for (int it=0; it<8; it++){
      int row = ldrow + it*32;
      cpa16(st + (uint32_t)(128+row)*144 + (uint32_t)ld16*16,
            Bt + (size_t)(n0+row)*CDIM + c2*64 + ld16*8);
    }
    cpa_commit();
  };

  issue(0, 0);
  issue(1, 1);

  for (int c=0; c<32; c++){
    if (c==31) asm volatile("cp.async.wait_group 0;" ::: "memory");
    else       asm volatile("cp.async.wait_group 1;" ::: "memory");
    __syncthreads();
    if (c+2 < 32) issue(c+2, (c+2)%NSTG);

    const uint32_t stb = sb + (c%NSTG)*STG_B;
    #pragma unroll
    for (int ks=0; ks<4; ks++){          // k16 step = 32B
      uint32_t a[4][4];
      #pragma unroll
      for (int mi=0; mi<4; mi++)
        ldm4(a[mi][0],a[mi][1],a[mi][2],a[mi][3], stb + aoff + mi*2304 + ks*32);
      #pragma unroll
      for (int pr=0; pr<4; pr++){
        uint32_t b0,b1,b2,b3;
        ldm4(b0,b1,b2,b3, stb + boff + pr*2304 + ks*32);
        #pragma unroll
        for (int mi=0; mi<4; mi++){
          mma_f16(d[mi][2*pr  ][0], d[mi][2*pr  ][1], d[mi][2*pr  ][2], d[mi][2*pr  ][3],
                  a[mi][0],a[mi][1],a[mi][2],a[mi][3], b0, b1);
          mma_f16(d[mi][2*pr+1][0], d[mi][2*pr+1][1], d[mi][2*pr+1][2], d[mi][2*pr+1][3],
                  a[mi][0],a[mi][1],a[mi][2],a[mi][3], b2, b3);
        }
      }
    }
  }

  #pragma unroll
  for (int mi=0; mi<4; mi++){
    int row = cRow + wm*64 + mi*16 + g;
    #pragma unroll
    for (int ni=0; ni<8; ni++){
      int col = n0 + wn*64 + ni*8 + cc*2;
      *(float2*)(C + (size_t)row*Ntot + col) =
          make_float2(d[mi][ni][0], d[mi][ni][1]);
      *(float2*)(C + (size_t)(row+8)*Ntot + col) =
          make_float2(d[mi][ni][2], d[mi][ni][3]);
    }
  }
}

__global__ __launch_bounds__(256,1) void gemm_qkv_f16(){
  const int z = blockIdx.x >> 3;
  const int n = blockIdx.x & 7;
  const __half* Bt = g_wth + (size_t)z * CDIM * CDIM;
  float* Cc = g_xqkv + (size_t)z * (size_t)BL * CDIM;
  gemm_f16_body(g_Hh, Bt, Cc, CDIM, n*256, blockIdx.y*128);
}
__global__ __launch_bounds__(256,1) void gemm_out_f16(float* __restrict__ out){
  gemm_f16_body(g_Yh, g_woh, out, ODIM, blockIdx.x*256, blockIdx.y*128);
}

// ============================================================
// prep: transpose -> fp16 ; H -> fp16
// ============================================================
__global__ __launch_bounds__(256) void transpose_h(
    const float* __restrict__ in, __half* __restrict__ out, int R, int C)
{
  __shared__ float tile[32][33];
  int c0 = blockIdx.x*32, r0 = blockIdx.y*32;
  int tx = threadIdx.x & 31, ty = threadIdx.x >> 5;
  for (int i=ty; i<32; i+=8) tile[i][tx] = in[(size_t)(r0+i)*C + c0 + tx];
  __syncthreads();
  for (int i=ty; i<32; i+=8)
    out[(size_t)(c0+i)*R + r0 + tx] = __float2half_rn(tile[tx][i]);
}

__global__ __launch_bounds__(256) void half_H(const float* __restrict__ in){
  size_t i = ((size_t)blockIdx.x*256 + threadIdx.x)*4;
  float4 v = *(const float4*)(in + i);
  __half2 h0 = __floats2half2_rn(v.x, v.y);
  __half2 h1 = __floats2half2_rn(v.z, v.w);
  *(__half2*)(g_Hh + i)     = h0;
  *(__half2*)(g_Hh + i + 2) = h1;
}

// ============================================================
// lr dot: out[row, h] = sum_c X[row,c] * lrw[h,c]
// ============================================================
__global__ __launch_bounds__(256) void lr_gemm(
    const float* __restrict__ X, const float* __restrict__ Wl)
{
  __shared__ float Xs[64][65];
  __shared__ float Ws[64][33];
  int t = threadIdx.x;
  int row0 = blockIdx.x * 64;
  float acc[8];
  #pragma unroll
  for (int r=0;r<8;r++) acc[r]=0.f;
  int rBase = (t >> 5) * 8;
  int hCol  = t & 31;
  for (int k0=0;k0<CDIM;k0+=64){
    for (int e=t;e<1024;e+=256){
      int r = e >> 4; int c4 = (e & 15)*4;
      float4 v = *(const float4*)(X + (size_t)(row0+r)*CDIM + k0 + c4);
      Xs[r][c4+0]=v.x; Xs[r][c4+1]=v.y; Xs[r][c4+2]=v.z; Xs[r][c4+3]=v.w;
    }
    for (int e=t;e<512;e+=256){
      int hh = e >> 4; int c4 = (e & 15)*4;
      float4 v = *(const float4*)(Wl + (size_t)hh*CDIM + k0 + c4);
      Ws[c4+0][hh]=v.x; Ws[c4+1][hh]=v.y; Ws[c4+2][hh]=v.z; Ws[c4+3][hh]=v.w;
    }
    __syncthreads();
    #pragma unroll 16
    for (int k=0;k<64;k++){
      float w = Ws[k][hCol];
      #pragma unroll
      for (int r=0;r<8;r++) acc[r] = fmaf(Xs[rBase+r][k], w, acc[r]);
    }
    __syncthreads();
  }
  #pragma unroll
  for (int r=0;r<8;r++)
    g_lr[(size_t)(row0+rBase+r)*NHEADS + hCol] = acc[r];
}

// ============================================================
// TTT scan (R14 split-W version, validated): one block per (b,h).
// ============================================================
#define SCAN_SM (16624*4)

__global__ __launch_bounds__(256) void ttt_scan(
  const int*   __restrict__ pid,
  const float* __restrict__ W1in, const float* __restrict__ b1in,
  const float* __restrict__ lrb,  const float* __restrict__ ltid,
  const float* __restrict__ lnw,  const float* __restrict__ lnb)
{
  extern __shared__ float sm[];
  float (*Whs)[72] = (float(*)[72])(sm);
  float (*Wls)[72] = (float(*)[72])(sm + 4608);
  float (*gr )[72] = (float(*)[72])(sm + 9216);
  float (*xq )[68] = (float(*)[68])(sm + 10368);
  float (*xk )[68] = (float(*)[68])(sm + 11456);
  float (*xv )[68] = (float(*)[68])(sm + 12544);
  float (*zz )[68] = (float(*)[68])(sm + 13632);
  float (*attn)[20] = (float(*)[20])(sm + 14720);
  float (*Smat)[20] = (float(*)[20])(sm + 15040);
  float* b1s = sm + 15360;
  float* gam = sm + 15424;
  float* bet = sm + 15488;
  float* etalr = sm + 15552;
  float* ce  = sm + 15568;
  float* tok = sm + 15584;
  float (*ctab)[32] = (float(*)[32])(sm + 15600);
  float (*stab)[32] = (float(*)[32])(sm + 16112);

  int b = blockIdx.x >> 5;
  int h = blockIdx.x & 31;
  int t = threadIdx.x;
  int w = t >> 5, lane = t & 31;
  int g = lane >> 2, cc = lane & 3;

  const int m0 = 16*(w & 3);
  const int nbase = 32*(w >> 2);
  float accw[4][4];
  #pragma unroll
  for (int nt=0; nt<4; nt++){
    int nu = nbase + 8*nt;
    accw[nt][0] = W1in[(size_t)h*4096 + (m0+g  )*64 + nu+2*cc  ];
    accw[nt][1] = W1in[(size_t)h*4096 + (m0+g  )*64 + nu+2*cc+1];
    accw[nt][2] = W1in[(size_t)h*4096 + (m0+8+g)*64 + nu+2*cc  ];
    accw[nt][3] = W1in[(size_t)h*4096 + (m0+8+g)*64 + nu+2*cc+1];
  }
  if (t<64){ b1s[t]=b1in[h*64+t]; gam[t]=lnw[h*64+t]; bet[t]=lnb[h*64+t]; }
  if (t<16) tok[t] = fmaxf(1.f/(float)(t+1) + ltid[t], 0.f);
  for (int e=t;e<512;e+=256){
    int p = e >> 5, pi = e & 31;
    float inv = exp2f(-13.287712379549449f * (float)(2*pi) * (1.f/64.f));
    float ang = (float)p * inv;
    ctab[p][pi] = cosf(ang); stab[p][pi] = sinf(ang);
  }
  float lrbias = lrb[h];
  __syncthreads();

  const size_t PL = (size_t)BL*CDIM;
  const float* XQp = g_xqkv;
  const float* XKp = g_xqkv + PL;
  const float* XVp = g_xqkv + 2*PL;

  for (int m=0;m<NMB;m++){
    int l0 = m*MBSZ;
    // ---------- phase A: emit Wh/Wl; load tiles + RoPE ----------
    #pragma unroll
    for (int nt=0; nt<4; nt++){
      int nu = nbase + 8*nt;
      #pragma unroll
      for (int j=0;j<4;j++){
        int rr = m0 + ((j & 2) ? 8+g : g);
        int ccol = nu + 2*cc + (j & 1);
        float v = accw[nt][j];
        float hf = __uint_as_float(tfu(v));
        Whs[rr][ccol] = hf;
        Wls[rr][ccol] = __uint_as_float(tfu(v - hf));
      }
    }
    for (int p=t;p<512;p+=256){
      int i = p >> 5, pi = p & 31;
      size_t base = ((size_t)b*LSEQ + l0 + i)*CDIM + h*64 + 2*pi;
      int pos = pid[(size_t)b*LSEQ + l0 + i] & 15;
      float c = ctab[pos][pi], s = stab[pos][pi];
      float q0=XQp[base], q1=XQp[base+1];
      xq[i][2*pi]   = q0*c - q1*s;
      xq[i][2*pi+1] = q1*c + q0*s;
      float k0=XKp[base], k1=XKp[base+1];
      xk[i][2*pi]   = k0*c - k1*s;
      xk[i][2*pi+1] = k1*c + k0*s;
    }
    for (int e=t;e<512;e+=256){
      int i = e >> 5, d2 = (e & 31)*2;
      float2 v = *(const float2*)(XVp + ((size_t)b*LSEQ + l0 + i)*CDIM + h*64 + d2);
      xv[i][d2] = v.x; xv[i][d2+1] = v.y;
    }
    if (t<16){
      float x = g_lr[((size_t)b*LSEQ + l0 + t)*NHEADS + h] + lrbias;
      float e = (1.f/(1.f+expf(-x))) * (1.f/64.f);
      etalr[t]=e; ce[t]=tok[15]*e;
    }
    __syncthreads();
    // ---------- phase B ----------
    {
      const int n0 = w*8;
      float d0 = b1s[n0+2*cc], d1 = b1s[n0+2*cc+1];
      float d2 = d0, d3 = d1;
      #pragma unroll
      for (int ks=0; ks<8; ks++){
        const int kk = ks*8;
        uint32_t a0 = tfu(xk[g  ][kk+cc  ]), a1 = tfu(xk[8+g][kk+cc  ]);
        uint32_t a2 = tfu(xk[g  ][kk+cc+4]), a3 = tfu(xk[8+g][kk+cc+4]);
        uint32_t bh0 = __float_as_uint(Whs[kk+cc][n0+g]);
        uint32_t bh1 = __float_as_uint(Whs[kk+cc+4][n0+g]);
        uint32_t bl0 = __float_as_uint(Wls[kk+cc][n0+g]);
        uint32_t bl1 = __float_as_uint(Wls[kk+cc+4][n0+g]);
        mma_tf32(d0,d1,d2,d3, a0,a1,a2,a3, bh0,bh1);
        mma_tf32(d0,d1,d2,d3, a0,a1,a2,a3, bl0,bl1);
      }
      zz[g  ][n0+2*cc]=d0; zz[g  ][n0+2*cc+1]=d1;
      zz[8+g][n0+2*cc]=d2; zz[8+g][n0+2*cc+1]=d3;
      if (w < 2){
        const int na = w*8;
        float e0=0.f,e1=0.f,e2=0.f,e3=0.f;
        #pragma unroll
        for (int ks=0; ks<8; ks++){
          const int kk = ks*8;
          uint32_t a0 = tfu(xq[g  ][kk+cc  ]), a1 = tfu(xq[8+g][kk+cc  ]);
          uint32_t a2 = tfu(xq[g  ][kk+cc+4]), a3 = tfu(xq[8+g][kk+cc+4]);
          uint32_t b0 = tfu(xk[na+g][kk+cc ]), b1f= tfu(xk[na+g][kk+cc+4]);
          mma_tf32(e0,e1,e2,e3, a0,a1,a2,a3, b0,b1f);
        }
        attn[g  ][na+2*cc]=e0; attn[g  ][na+2*cc+1]=e1;
        attn[8+g][na+2*cc]=e2; attn[8+g][na+2*cc+1]=e3;
      }
    }
    __syncthreads();
    // ---------- phase C ----------
    {
      int i = t >> 4, j = t & 15;
      Smat[i][j] = (j <= i) ? -tok[i]*etalr[j]*(attn[i][j] + 1.f) : 0.f;
    }
    {
      for (int i=w;i<16;i+=8){
        float v0 = zz[i][lane], v1 = zz[i][lane+32];
        float sm2 = v0+v1, sq = v0*v0+v1*v1;
        #pragma unroll
        for (int o=16;o;o>>=1){ sm2 += __shfl_xor_sync(~0u, sm2, o); sq += __shfl_xor_sync(~0u, sq, o); }
        float mu = sm2 * (1.f/64.f);
        float var = sq * (1.f/64.f) - mu*mu;
        float rstd = rsqrtf(var + EPSV);
        float xh0 = (v0-mu)*rstd, xh1 = (v1-mu)*rstd;
        float g0 = gam[lane], g1 = gam[lane+32];
        float y0 = g0*xh0 + bet[lane], y1 = g1*xh1 + bet[lane+32];
        float tg0 = (y0 - (xv[i][lane]    - xk[i][lane]   )) * g0;
        float tg1 = (y1 - (xv[i][lane+32] - xk[i][lane+32])) * g1;
        float sg = tg0+tg1, sgx = tg0*xh0 + tg1*xh1;
        #pragma unroll
        for (int o=16;o;o>>=1){ sg += __shfl_xor_sync(~0u, sg, o); sgx += __shfl_xor_sync(~0u, sgx, o); }
        float sc = rstd * (1.f/64.f);
        gr[i][lane]    = (64.f*tg0 - sg - xh0*sgx) * sc;
        gr[i][lane+32] = (64.f*tg1 - sg - xh1*sgx) * sc;
      }
    }
    __syncthreads();
    // ---------- phase D ----------
    {
      const int n0 = w*8;
      float d0 = b1s[n0+2*cc], d1 = b1s[n0+2*cc+1];
      float d2 = d0, d3 = d1;
      #pragma unroll
      for (int ks=0; ks<8; ks++){
        const int kk = ks*8;
        uint32_t a0 = tfu(xq[g  ][kk+cc  ]), a1 = tfu(xq[8+g][kk+cc  ]);
        uint32_t a2 = tfu(xq[g  ][kk+cc+4]), a3 = tfu(xq[8+g][kk+cc+4]);
        uint32_t bh0 = __float_as_uint(Whs[kk+cc][n0+g]);
        uint32_t bh1 = __float_as_uint(Whs[kk+cc+4][n0+g]);
        uint32_t bl0 = __float_as_uint(Wls[kk+cc][n0+g]);
        uint32_t bl1 = __float_as_uint(Wls[kk+cc+4][n0+g]);
        mma_tf32(d0,d1,d2,d3, a0,a1,a2,a3, bh0,bh1);
        mma_tf32(d0,d1,d2,d3, a0,a1,a2,a3, bl0,bl1);
      }
      #pragma unroll
      for (int ks=0; ks<2; ks++){
        const int kk = ks*8;
        uint32_t a0 = tfu(Smat[g  ][kk+cc  ]), a1 = tfu(Smat[8+g][kk+cc  ]);
        uint32_t a2 = tfu(Smat[g  ][kk+cc+4]), a3 = tfu(Smat[8+g][kk+cc+4]);
        uint32_t b0 = tfu(gr[kk+cc][n0+g]),   b1f= tfu(gr[kk+cc+4][n0+g]);
        mma_tf32(d0,d1,d2,d3, a0,a1,a2,a3, b0,b1f);
      }
      zz[g  ][n0+2*cc]=d0; zz[g  ][n0+2*cc+1]=d1;
      zz[8+g][n0+2*cc]=d2; zz[8+g][n0+2*cc+1]=d3;
    }
    __syncthreads();
    // ---------- phase E ----------
    {
      for (int i=w;i<16;i+=8){
        float v0 = zz[i][lane], v1 = zz[i][lane+32];
        float sm2 = v0+v1, sq = v0*v0+v1*v1;
        #pragma unroll
        for (int o=16;o;o>>=1){ sm2 += __shfl_xor_sync(~0u, sm2, o); sq += __shfl_xor_sync(~0u, sq, o); }
        float mu = sm2*(1.f/64.f);
        float rstd = rsqrtf(sq*(1.f/64.f) - mu*mu + EPSV);
        size_t orow = ((size_t)b*LSEQ + l0 + i)*CDIM + h*64;
        g_Y[orow+lane]    = xq[i][lane]    + gam[lane]   *((v0-mu)*rstd) + bet[lane];
        g_Y[orow+lane+32] = xq[i][lane+32] + gam[lane+32]*((v1-mu)*rstd) + bet[lane+32];
      }
      uint32_t ua[2][4];
      #pragma unroll
      for (int ks=0; ks<2; ks++){
        const int kk = ks*8;
        ua[ks][0] = tfu(-ce[kk+cc  ] * xk[kk+cc  ][m0+g  ]);
        ua[ks][1] = tfu(-ce[kk+cc  ] * xk[kk+cc  ][m0+8+g]);
        ua[ks][2] = tfu(-ce[kk+cc+4] * xk[kk+cc+4][m0+g  ]);
        ua[ks][3] = tfu(-ce[kk+cc+4] * xk[kk+cc+4][m0+8+g]);
      }
      #pragma unroll
      for (int nt=0; nt<4; nt++){
        const int nu = nbase + 8*nt;
        #pragma unroll
        for (int ks=0; ks<2; ks++){
          const int kk = ks*8;
          uint32_t b0 = tfu(gr[kk+cc][nu+g]), b1f = tfu(gr[kk+cc+4][nu+g]);
          mma_tf32(accw[nt][0],accw[nt][1],accw[nt][2],accw[nt][3],
                   ua[ks][0],ua[ks][1],ua[ks][2],ua[ks][3], b0,b1f);
        }
      }
      if (t<64){
        float a = b1s[t];
        #pragma unroll
        for (int j=0;j<16;j++) a = fmaf(-ce[j], gr[j][t], a);
        b1s[t] = a;
      }
    }
    __syncthreads();
  }
}

// ============================================================
// Post layernorm over C=2048 per row -> fp16 for out-GEMM
// ============================================================
__global__ __launch_bounds__(256) void rownorm(
    const float* __restrict__ w, const float* __restrict__ bias)
{
  int row = blockIdx.x; int t = threadIdx.x;
  const float* rp = g_Y + (size_t)row * CDIM;
  float s=0.f, ss=0.f;
  for (int c=t;c<CDIM;c+=256){ float v = rp[c]; s+=v; ss=fmaf(v,v,ss); }
  #pragma unroll
  for (int o=16;o;o>>=1){ s += __shfl_xor_sync(~0u,s,o); ss += __shfl_xor_sync(~0u,ss,o); }
  __shared__ float sw[8], ssw[8];
  int wid=t>>5, lane=t&31;
  if (lane==0){ sw[wid]=s; ssw[wid]=ss; }
  __syncthreads();
  float ts=0.f, tss=0.f;
  #pragma unroll
  for (int i2=0;i2<8;i2++){ ts+=sw[i2]; tss+=ssw[i2]; }
  float mu = ts*(1.f/CDIM);
  float rstd = rsqrtf(tss*(1.f/CDIM) - mu*mu + EPSV);
  __half* op = g_Yh + (size_t)row*CDIM;
  for (int c=t;c<CDIM;c+=256){
    float v=rp[c];
    op[c] = __float2half_rn((v-mu)*rstd*w[c] + bias[c]);
  }
}

// ============================================================
extern "C" void kernel_launch(void* const* d_in, const int* in_sizes, int n_in,
                              void* d_out, int out_size)
{
  const float* H   = (const float*)d_in[0];
  const int*   pid = (const int*)  d_in[1];
  const float* Wq  = (const float*)d_in[2];
  const float* Wk  = (const float*)d_in[3];
  const float* Wv  = (const float*)d_in[4];
  const float* Wo  = (const float*)d_in[5];
  const float* W1  = (const float*)d_in[6];
  const float* b1  = (const float*)d_in[7];
  const float* lrw = (const float*)d_in[8];
  const float* lrb = (const float*)d_in[9];
  const float* lti = (const float*)d_in[10];
  const float* lnw = (const float*)d_in[11];
  const float* lnb = (const float*)d_in[12];
  const float* pnw = (const float*)d_in[13];
  const float* pnb = (const float*)d_in[14];
  float* out = (float*)d_out;
  (void)in_sizes; (void)n_in; (void)out_size;

  static bool attr_set = false;
  if (!attr_set){
    cudaFuncSetAttribute(gemm_qkv_f16, cudaFuncAttributeMaxDynamicSharedMemorySize, SM_GTOT);
    cudaFuncSetAttribute(gemm_out_f16, cudaFuncAttributeMaxDynamicSharedMemorySize, SM_GTOT);
    cudaFuncSetAttribute(ttt_scan,     cudaFuncAttributeMaxDynamicSharedMemorySize, SCAN_SM);
    attr_set = true;
  }

  __half* wth = nullptr; cudaGetSymbolAddress((void**)&wth, g_wth);
  __half* woh = nullptr; cudaGetSymbolAddress((void**)&woh, g_woh);

  transpose_h<<<dim3(64,64), 256>>>(Wq, wth,                        CDIM, CDIM);
  transpose_h<<<dim3(64,64), 256>>>(Wk, wth + (size_t)CDIM*CDIM,    CDIM, CDIM);
  transpose_h<<<dim3(64,64), 256>>>(Wv, wth + (size_t)2*CDIM*CDIM,  CDIM, CDIM);
  transpose_h<<<dim3(24,64), 256>>>(Wo, woh,                        CDIM, ODIM);
  half_H<<<(BL*(size_t)CDIM)/(256*4), 256>>>(H);

  gemm_qkv_f16<<<dim3(24, BL/128), 256, SM_GTOT>>>();
  lr_gemm<<<BL/64, 256>>>(H, lrw);
  ttt_scan<<<BDIM*NHEADS, 256, SCAN_SM>>>(pid, W1, b1, lrb, lti, lnw, lnb);
  rownorm<<<BL, 256>>>(pnw, pnb);
  gemm_out_f16<<<dim3(ODIM/256, BL/128), 256, SM_GTOT>>>(out);
}

// round 17
// speedup vs baseline: 1.8900x; 1.0943x over previous
#include <cuda_runtime.h>
#include <cuda_fp16.h>
#include <cstdint>
#include <cstddef>

#define NHEADS 32
#define HDIM 64
#define MBSZ 16
#define BDIM 4
#define LSEQ 2048
#define CDIM 2048
#define ODIM 768
#define NMB (LSEQ/MBSZ)
#define BL (BDIM*LSEQ)
#define EPSV 1e-6f

// -------- scratch (device globals; no allocations allowed) --------
__device__ float g_xqkv[(size_t)3*BL*CDIM];  // XQ | XK | XV, each [BL, C]
__device__ float g_lr[(size_t)BL*NHEADS];    // lr dot per (token, head)
__device__ float g_Y[(size_t)BL*CDIM];       // scan output, [B,L,C]
__device__ __half g_Hh[(size_t)BL*CDIM];     // H as fp16
__device__ __half g_wth[(size_t)3*CDIM*CDIM];// Wq^T|Wk^T|Wv^T fp16, [N][K]
__device__ __half g_woh[(size_t)ODIM*CDIM];  // Wo^T fp16
__device__ __half g_Yh[(size_t)BL*CDIM];     // post-norm fp16

// ============================================================
// helpers
// ============================================================
__device__ __forceinline__ uint32_t tfu(float x){
  uint32_t u; asm("cvt.rna.tf32.f32 %0, %1;" : "=r"(u) : "f"(x));
  return u;
}
__device__ __forceinline__ void mma_tf32(float& d0, float& d1, float& d2, float& d3,
                                         uint32_t a0, uint32_t a1, uint32_t a2, uint32_t a3,
                                         uint32_t b0, uint32_t b1){
  asm volatile(
    "mma.sync.aligned.m16n8k8.row.col.f32.tf32.tf32.f32 "
    "{%0,%1,%2,%3}, {%4,%5,%6,%7}, {%8,%9}, {%0,%1,%2,%3};"
    : "+f"(d0), "+f"(d1), "+f"(d2), "+f"(d3)
    : "r"(a0), "r"(a1), "r"(a2), "r"(a3), "r"(b0), "r"(b1));
}
__device__ __forceinline__ void mma_f16(float& d0, float& d1, float& d2, float& d3,
                                        uint32_t a0, uint32_t a1, uint32_t a2, uint32_t a3,
                                        uint32_t b0, uint32_t b1){
  asm volatile(
    "mma.sync.aligned.m16n8k16.row.col.f32.f16.f16.f32 "
    "{%0,%1,%2,%3}, {%4,%5,%6,%7}, {%8,%9}, {%0,%1,%2,%3};"
    : "+f"(d0), "+f"(d1), "+f"(d2), "+f"(d3)
    : "r"(a0), "r"(a1), "r"(a2), "r"(a3), "r"(b0), "r"(b1));
}
__device__ __forceinline__ void ldm4(uint32_t& r0, uint32_t& r1, uint32_t& r2, uint32_t& r3,
                                     uint32_t addr){
  asm volatile("ldmatrix.sync.aligned.m8n8.x4.shared.b16 {%0,%1,%2,%3}, [%4];"
    : "=r"(r0), "=r"(r1), "=r"(r2), "=r"(r3) : "r"(addr));
}
__device__ __forceinline__ uint32_t smem_u32(const void* p){
  uint32_t a;
  asm("{ .reg .u64 t; cvta.to.shared.u64 t, %1; cvt.u32.u64 %0, t; }" : "=r"(a) : "l"(p));
  return a;
}
__device__ __forceinline__ void cpa16(uint32_t dst, const void* src){
  asm volatile("cp.async.cg.shared.global [%0], [%1], 16;" :: "r"(dst), "l"(src));
}
__device__ __forceinline__ void cpa_commit(){
  asm volatile("cp.async.commit_group;" ::: "memory");
}

// SMEM tile: rows of 64 fp16 = 128B payload, padded to 144B
// templated on MR (A rows per CTA): stage = (MR + 256) rows
#define NSTG 3
#define STG_B(MR)  (((MR)+256)*144)
#define SM_G(MR)   (NSTG*STG_B(MR))
#define SM_GTOT    SM_G(128)            // 165888 (max)

// ============================================================
// fp16 GEMM: C[M,Ntot] = A[M,2048] @ Bt[Ntot,2048]^T (fp32 accum)
// CTA tile MRx256, 256 threads (8 warps: 2m x 4n), warp tile (MR/2)x64
// K-chunk 64; fragments via ldmatrix.b16; 3-stage cp.async pipeline
// ============================================================
template<int MR>
__device__ __forceinline__ void gemm_f16_body(
    const __half* __restrict__ A, const __half* __restrict__ Bt,
    float* __restrict__ C, int Ntot, int n0, int cRow)
{
  constexpr int MI   = MR/32;          // m16 tiles per warp (4 or 2)
  constexpr int ASTB = MR*144;

  extern __shared__ float smem[];
  const uint32_t sb = smem_u32(smem);

  const int t    = threadIdx.x;
  const int wid  = t >> 5, lane = t & 31;
  const int wm   = wid & 1;        // 0..1 -> (MR/2)-row slab
  const int wn   = wid >> 1;       // 0..3 -> 64-col slab
  const int g    = lane >> 2;
  const int cc   = lane & 3;

  const int ldrow = t >> 3;        // 0..31
  const int ld16  = t & 7;         // 16B unit within 128B payload

  const uint32_t aoff = (uint32_t)(wm*(MR/2) + (lane & 15))*144 + (uint32_t)(lane >> 4)*16;
  const uint32_t boff = (uint32_t)ASTB
      + (uint32_t)(wn*64 + ((lane & 16) ? 8 : 0) + (lane & 7))*144
      + (uint32_t)((lane & 8) ? 16 : 0);

  float d[MI][8][4];
  #pragma unroll
  for (int mi=0;mi<MI;mi++)
    #pragma unroll
    for (int ni=0;ni<8;ni++)
      #pragma unroll
      for (int r=0;r<4;r++) d[mi][ni][r]=0.f;

  auto issue = [&](int c2, int buf){
    const uint32_t st = sb + buf*STG_B(MR);
    #pragma unroll
    for (int it=0; it<MR/32; it++){
      int row = ldrow + it*32;
      cpa16(st + (uint32_t)row*144 + (uint32_t)ld16*16,
            A + (size_t)(cRow+row)*CDIM + c2*64 + ld16*8);
    }
    #pragma unroll
    for (int it=0; it<8; it++){
      int row = ldrow + it*32;
      cpa16(st + (uint32_t)(MR+row)*144 + (uint32_t)ld16*16,
            Bt + (size_t)(n0+row)*CDIM + c2*64 + ld16*8);
    }
    cpa_commit();
  };

  issue(0, 0);
  issue(1, 1);

  for (int c=0; c<32; c++){
    if (c==31) asm volatile("cp.async.wait_group 0;" ::: "memory");
    else       asm volatile("cp.async.wait_group 1;" ::: "memory");
    __syncthreads();
    if (c+2 < 32) issue(c+2, (c+2)%NSTG);

    const uint32_t stb = sb + (c%NSTG)*STG_B(MR);
    #pragma unroll
    for (int ks=0; ks<4; ks++){          // k16 step = 32B
      uint32_t a[MI][4];
      #pragma unroll
      for (int mi=0; mi<MI; mi++)
        ldm4(a[mi][0],a[mi][1],a[mi][2],a[mi][3], stb + aoff + mi*2304 + ks*32);
      #pragma unroll
      for (int pr=0; pr<4; pr++){
        uint32_t b0,b1,b2,b3;
        ldm4(b0,b1,b2,b3, stb + boff + pr*2304 + ks*32);
        #pragma unroll
        for (int mi=0; mi<MI; mi++){
          mma_f16(d[mi][2*pr  ][0], d[mi][2*pr  ][1], d[mi][2*pr  ][2], d[mi][2*pr  ][3],
                  a[mi][0],a[mi][1],a[mi][2],a[mi][3], b0, b1);
          mma_f16(d[mi][2*pr+1][0], d[mi][2*pr+1][1], d[mi][2*pr+1][2], d[mi][2*pr+1][3],
                  a[mi][0],a[mi][1],a[mi][2],a[mi][3], b2, b3);
        }
      }
    }
  }

  #pragma unroll
  for (int mi=0; mi<MI; mi++){
    int row = cRow + wm*(MR/2) + mi*16 + g;
    #pragma unroll
    for (int ni=0; ni<8; ni++){
      int col = n0 + wn*64 + ni*8 + cc*2;
      *(float2*)(C + (size_t)row*Ntot + col) =
          make_float2(d[mi][ni][0], d[mi][ni][1]);
      *(float2*)(C + (size_t)(row+8)*Ntot + col) =
          make_float2(d[mi][ni][2], d[mi][ni][3]);
    }
  }
}

__global__ __launch_bounds__(256,1) void gemm_qkv_f16(){
  const int z = blockIdx.x >> 3;
  const int n = blockIdx.x & 7;
  const __half* Bt = g_wth + (size_t)z * CDIM * CDIM;
  float* Cc = g_xqkv + (size_t)z * (size_t)BL * CDIM;
  gemm_f16_body<128>(g_Hh, Bt, Cc, CDIM, n*256, blockIdx.y*128);
}
__global__ __launch_bounds__(256,1) void gemm_out_f16(float* __restrict__ out){
  gemm_f16_body<64>(g_Yh, g_woh, out, ODIM, blockIdx.x*256, blockIdx.y*64);
}

// ============================================================
// prep: transpose -> fp16 ; H -> fp16
// ============================================================
__global__ __launch_bounds__(256) void transpose_h(
    const float* __restrict__ in, __half* __restrict__ out, int R, int C)
{
  __shared__ float tile[32][33];
  int c0 = blockIdx.x*32, r0 = blockIdx.y*32;
  int tx = threadIdx.x & 31, ty = threadIdx.x >> 5;
  for (int i=ty; i<32; i+=8) tile[i][tx] = in[(size_t)(r0+i)*C + c0 + tx];
  __syncthreads();
  for (int i=ty; i<32; i+=8)
    out[(size_t)(c0+i)*R + r0 + tx] = __float2half_rn(tile[tx][i]);
}

__global__ __launch_bounds__(256) void half_H(const float* __restrict__ in){
  size_t i = ((size_t)blockIdx.x*256 + threadIdx.x)*4;
  float4 v = *(const float4*)(in + i);
  __half2 h0 = __floats2half2_rn(v.x, v.y);
  __half2 h1 = __floats2half2_rn(v.z, v.w);
  *(__half2*)(g_Hh + i)     = h0;
  *(__half2*)(g_Hh + i + 2) = h1;
}

// ============================================================
// lr dot: out[row, h] = sum_c X[row,c] * lrw[h,c]
// ============================================================
__global__ __launch_bounds__(256) void lr_gemm(
    const float* __restrict__ X, const float* __restrict__ Wl)
{
  __shared__ float Xs[64][65];
  __shared__ float Ws[64][33];
  int t = threadIdx.x;
  int row0 = blockIdx.x * 64;
  float acc[8];
  #pragma unroll
  for (int r=0;r<8;r++) acc[r]=0.f;
  int rBase = (t >> 5) * 8;
  int hCol  = t & 31;
  for (int k0=0;k0<CDIM;k0+=64){
    for (int e=t;e<1024;e+=256){
      int r = e >> 4; int c4 = (e & 15)*4;
      float4 v = *(const float4*)(X + (size_t)(row0+r)*CDIM + k0 + c4);
      Xs[r][c4+0]=v.x; Xs[r][c4+1]=v.y; Xs[r][c4+2]=v.z; Xs[r][c4+3]=v.w;
    }
    for (int e=t;e<512;e+=256){
      int hh = e >> 4; int c4 = (e & 15)*4;
      float4 v = *(const float4*)(Wl + (size_t)hh*CDIM + k0 + c4);
      Ws[c4+0][hh]=v.x; Ws[c4+1][hh]=v.y; Ws[c4+2][hh]=v.z; Ws[c4+3][hh]=v.w;
    }
    __syncthreads();
    #pragma unroll 16
    for (int k=0;k<64;k++){
      float w = Ws[k][hCol];
      #pragma unroll
      for (int r=0;r<8;r++) acc[r] = fmaf(Xs[rBase+r][k], w, acc[r]);
    }
    __syncthreads();
  }
  #pragma unroll
  for (int r=0;r<8;r++)
    g_lr[(size_t)(row0+rBase+r)*NHEADS + hCol] = acc[r];
}

// ============================================================
// TTT scan (validated R14/R15 split-W version): one block per (b,h).
// ============================================================
#define SCAN_SM (16624*4)

__global__ __launch_bounds__(256) void ttt_scan(
  const int*   __restrict__ pid,
  const float* __restrict__ W1in, const float* __restrict__ b1in,
  const float* __restrict__ lrb,  const float* __restrict__ ltid,
  const float* __restrict__ lnw,  const float* __restrict__ lnb)
{
  extern __shared__ float sm[];
  float (*Whs)[72] = (float(*)[72])(sm);
  float (*Wls)[72] = (float(*)[72])(sm + 4608);
  float (*gr )[72] = (float(*)[72])(sm + 9216);
  float (*xq )[68] = (float(*)[68])(sm + 10368);
  float (*xk )[68] = (float(*)[68])(sm + 11456);
  float (*xv )[68] = (float(*)[68])(sm + 12544);
  float (*zz )[68] = (float(*)[68])(sm + 13632);
  float (*attn)[20] = (float(*)[20])(sm + 14720);
  float (*Smat)[20] = (float(*)[20])(sm + 15040);
  float* b1s = sm + 15360;
  float* gam = sm + 15424;
  float* bet = sm + 15488;
  float* etalr = sm + 15552;
  float* ce  = sm + 15568;
  float* tok = sm + 15584;
  float (*ctab)[32] = (float(*)[32])(sm + 15600);
  float (*stab)[32] = (float(*)[32])(sm + 16112);

  int b = blockIdx.x >> 5;
  int h = blockIdx.x & 31;
  int t = threadIdx.x;
  int w = t >> 5, lane = t & 31;
  int g = lane >> 2, cc = lane & 3;

  const int m0 = 16*(w & 3);
  const int nbase = 32*(w >> 2);
  float accw[4][4];
  #pragma unroll
  for (int nt=0; nt<4; nt++){
    int nu = nbase + 8*nt;
    accw[nt][0] = W1in[(size_t)h*4096 + (m0+g  )*64 + nu+2*cc  ];
    accw[nt][1] = W1in[(size_t)h*4096 + (m0+g  )*64 + nu+2*cc+1];
    accw[nt][2] = W1in[(size_t)h*4096 + (m0+8+g)*64 + nu+2*cc  ];
    accw[nt][3] = W1in[(size_t)h*4096 + (m0+8+g)*64 + nu+2*cc+1];
  }
  if (t<64){ b1s[t]=b1in[h*64+t]; gam[t]=lnw[h*64+t]; bet[t]=lnb[h*64+t]; }
  if (t<16) tok[t] = fmaxf(1.f/(float)(t+1) + ltid[t], 0.f);
  for (int e=t;e<512;e+=256){
    int p = e >> 5, pi = e & 31;
    float inv = exp2f(-13.287712379549449f * (float)(2*pi) * (1.f/64.f));
    float ang = (float)p * inv;
    ctab[p][pi] = cosf(ang); stab[p][pi] = sinf(ang);
  }
  float lrbias = lrb[h];
  __syncthreads();

  const size_t PL = (size_t)BL*CDIM;
  const float* XQp = g_xqkv;
  const float* XKp = g_xqkv + PL;
  const float* XVp = g_xqkv + 2*PL;

  for (int m=0;m<NMB;m++){
    int l0 = m*MBSZ;
    // ---------- phase A ----------
    #pragma unroll
    for (int nt=0; nt<4; nt++){
      int nu = nbase + 8*nt;
      #pragma unroll
      for (int j=0;j<4;j++){
        int rr = m0 + ((j & 2) ? 8+g : g);
        int ccol = nu + 2*cc + (j & 1);
        float v = accw[nt][j];
        float hf = __uint_as_float(tfu(v));
        Whs[rr][ccol] = hf;
        Wls[rr][ccol] = __uint_as_float(tfu(v - hf));
      }
    }
    for (int p=t;p<512;p+=256){
      int i = p >> 5, pi = p & 31;
      size_t base = ((size_t)b*LSEQ + l0 + i)*CDIM + h*64 + 2*pi;
      int pos = pid[(size_t)b*LSEQ + l0 + i] & 15;
      float c = ctab[pos][pi], s = stab[pos][pi];
      float q0=XQp[base], q1=XQp[base+1];
      xq[i][2*pi]   = q0*c - q1*s;
      xq[i][2*pi+1] = q1*c + q0*s;
      float k0=XKp[base], k1=XKp[base+1];
      xk[i][2*pi]   = k0*c - k1*s;
      xk[i][2*pi+1] = k1*c + k0*s;
    }
    for (int e=t;e<512;e+=256){
      int i = e >> 5, d2 = (e & 31)*2;
      float2 v = *(const float2*)(XVp + ((size_t)b*LSEQ + l0 + i)*CDIM + h*64 + d2);
      xv[i][d2] = v.x; xv[i][d2+1] = v.y;
    }
    if (t<16){
      float x = g_lr[((size_t)b*LSEQ + l0 + t)*NHEADS + h] + lrbias;
      float e = (1.f/(1.f+expf(-x))) * (1.f/64.f);
      etalr[t]=e; ce[t]=tok[15]*e;
    }
    __syncthreads();
    // ---------- phase B ----------
    {
      const int n0 = w*8;
      float d0 = b1s[n0+2*cc], d1 = b1s[n0+2*cc+1];
      float d2 = d0, d3 = d1;
      #pragma unroll
      for (int ks=0; ks<8; ks++){
        const int kk = ks*8;
        uint32_t a0 = tfu(xk[g  ][kk+cc  ]), a1 = tfu(xk[8+g][kk+cc  ]);
        uint32_t a2 = tfu(xk[g  ][kk+cc+4]), a3 = tfu(xk[8+g][kk+cc+4]);
        uint32_t bh0 = __float_as_uint(Whs[kk+cc][n0+g]);
        uint32_t bh1 = __float_as_uint(Whs[kk+cc+4][n0+g]);
        uint32_t bl0 = __float_as_uint(Wls[kk+cc][n0+g]);
        uint32_t bl1 = __float_as_uint(Wls[kk+cc+4][n0+g]);
        mma_tf32(d0,d1,d2,d3, a0,a1,a2,a3, bh0,bh1);
        mma_tf32(d0,d1,d2,d3, a0,a1,a2,a3, bl0,bl1);
      }
      zz[g  ][n0+2*cc]=d0; zz[g  ][n0+2*cc+1]=d1;
      zz[8+g][n0+2*cc]=d2; zz[8+g][n0+2*cc+1]=d3;
      if (w < 2){
        const int na = w*8;
        float e0=0.f,e1=0.f,e2=0.f,e3=0.f;
        #pragma unroll
        for (int ks=0; ks<8; ks++){
          const int kk = ks*8;
          uint32_t a0 = tfu(xq[g  ][kk+cc  ]), a1 = tfu(xq[8+g][kk+cc  ]);
          uint32_t a2 = tfu(xq[g  ][kk+cc+4]), a3 = tfu(xq[8+g][kk+cc+4]);
          uint32_t b0 = tfu(xk[na+g][kk+cc ]), b1f= tfu(xk[na+g][kk+cc+4]);
          mma_tf32(e0,e1,e2,e3, a0,a1,a2,a3, b0,b1f);
        }
        attn[g  ][na+2*cc]=e0; attn[g  ][na+2*cc+1]=e1;
        attn[8+g][na+2*cc]=e2; attn[8+g][na+2*cc+1]=e3;
      }
    }
    __syncthreads();
    // ---------- phase C ----------
    {
      int i = t >> 4, j = t & 15;
      Smat[i][j] = (j <= i) ? -tok[i]*etalr[j]*(attn[i][j] + 1.f) : 0.f;
    }
    {
      for (int i=w;i<16;i+=8){
        float v0 = zz[i][lane], v1 = zz[i][lane+32];
        float sm2 = v0+v1, sq = v0*v0+v1*v1;
        #pragma unroll
        for (int o=16;o;o>>=1){ sm2 += __shfl_xor_sync(~0u, sm2, o); sq += __shfl_xor_sync(~0u, sq, o); }
        float mu = sm2 * (1.f/64.f);
        float var = sq * (1.f/64.f) - mu*mu;
        float rstd = rsqrtf(var + EPSV);
        float xh0 = (v0-mu)*rstd, xh1 = (v1-mu)*rstd;
        float g0 = gam[lane], g1 = gam[lane+32];
        float y0 = g0*xh0 + bet[lane], y1 = g1*xh1 + bet[lane+32];
        float tg0 = (y0 - (xv[i][lane]    - xk[i][lane]   )) * g0;
        float tg1 = (y1 - (xv[i][lane+32] - xk[i][lane+32])) * g1;
        float sg = tg0+tg1, sgx = tg0*xh0 + tg1*xh1;
        #pragma unroll
        for (int o=16;o;o>>=1){ sg += __shfl_xor_sync(~0u, sg, o); sgx += __shfl_xor_sync(~0u, sgx, o); }
        float sc = rstd * (1.f/64.f);
        gr[i][lane]    = (64.f*tg0 - sg - xh0*sgx) * sc;
        gr[i][lane+32] = (64.f*tg1 - sg - xh1*sgx) * sc;
      }
    }
    __syncthreads();
    // ---------- phase D ----------
    {
      const int n0 = w*8;
      float d0 = b1s[n0+2*cc], d1 = b1s[n0+2*cc+1];
      float d2 = d0, d3 = d1;
      #pragma unroll
      for (int ks=0; ks<8; ks++){
        const int kk = ks*8;
        uint32_t a0 = tfu(xq[g  ][kk+cc  ]), a1 = tfu(xq[8+g][kk+cc  ]);
        uint32_t a2 = tfu(xq[g  ][kk+cc+4]), a3 = tfu(xq[8+g][kk+cc+4]);
        uint32_t bh0 = __float_as_uint(Whs[kk+cc][n0+g]);
        uint32_t bh1 = __float_as_uint(Whs[kk+cc+4][n0+g]);
        uint32_t bl0 = __float_as_uint(Wls[kk+cc][n0+g]);
        uint32_t bl1 = __float_as_uint(Wls[kk+cc+4][n0+g]);
        mma_tf32(d0,d1,d2,d3, a0,a1,a2,a3, bh0,bh1);
        mma_tf32(d0,d1,d2,d3, a0,a1,a2,a3, bl0,bl1);
      }
      #pragma unroll
      for (int ks=0; ks<2; ks++){
        const int kk = ks*8;
        uint32_t a0 = tfu(Smat[g  ][kk+cc  ]), a1 = tfu(Smat[8+g][kk+cc  ]);
        uint32_t a2 = tfu(Smat[g  ][kk+cc+4]), a3 = tfu(Smat[8+g][kk+cc+4]);
        uint32_t b0 = tfu(gr[kk+cc][n0+g]),   b1f= tfu(gr[kk+cc+4][n0+g]);
        mma_tf32(d0,d1,d2,d3, a0,a1,a2,a3, b0,b1f);
      }
      zz[g  ][n0+2*cc]=d0; zz[g  ][n0+2*cc+1]=d1;
      zz[8+g][n0+2*cc]=d2; zz[8+g][n0+2*cc+1]=d3;
    }
    __syncthreads();
    // ---------- phase E ----------
    {
      for (int i=w;i<16;i+=8){
        float v0 = zz[i][lane], v1 = zz[i][lane+32];
        float sm2 = v0+v1, sq = v0*v0+v1*v1;
        #pragma unroll
        for (int o=16;o;o>>=1){ sm2 += __shfl_xor_sync(~0u, sm2, o); sq += __shfl_xor_sync(~0u, sq, o); }
        float mu = sm2*(1.f/64.f);
        float rstd = rsqrtf(sq*(1.f/64.f) - mu*mu + EPSV);
        size_t orow = ((size_t)b*LSEQ + l0 + i)*CDIM + h*64;
        g_Y[orow+lane]    = xq[i][lane]    + gam[lane]   *((v0-mu)*rstd) + bet[lane];
        g_Y[orow+lane+32] = xq[i][lane+32] + gam[lane+32]*((v1-mu)*rstd) + bet[lane+32];
      }
      uint32_t ua[2][4];
      #pragma unroll
      for (int ks=0; ks<2; ks++){
        const int kk = ks*8;
        ua[ks][0] = tfu(-ce[kk+cc  ] * xk[kk+cc  ][m0+g  ]);
        ua[ks][1] = tfu(-ce[kk+cc  ] * xk[kk+cc  ][m0+8+g]);
        ua[ks][2] = tfu(-ce[kk+cc+4] * xk[kk+cc+4][m0+g  ]);
        ua[ks][3] = tfu(-ce[kk+cc+4] * xk[kk+cc+4][m0+8+g]);
      }
      #pragma unroll
      for (int nt=0; nt<4; nt++){
        const int nu = nbase + 8*nt;
        #pragma unroll
        for (int ks=0; ks<2; ks++){
          const int kk = ks*8;
          uint32_t b0 = tfu(gr[kk+cc][nu+g]), b1f = tfu(gr[kk+cc+4][nu+g]);
          mma_tf32(accw[nt][0],accw[nt][1],accw[nt][2],accw[nt][3],
                   ua[ks][0],ua[ks][1],ua[ks][2],ua[ks][3], b0,b1f);
        }
      }
      if (t<64){
        float a = b1s[t];
        #pragma unroll
        for (int j=0;j<16;j++) a = fmaf(-ce[j], gr[j][t], a);
        b1s[t] = a;
      }
    }
    __syncthreads();
  }
}

// ============================================================
// Post layernorm over C=2048 per row -> fp16 for out-GEMM (float4 path)
// ============================================================
__global__ __launch_bounds__(256) void rownorm(
    const float* __restrict__ w, const float* __restrict__ bias)
{
  int row = blockIdx.x; int t = threadIdx.x;
  const float* rp = g_Y + (size_t)row * CDIM;
  float s=0.f, ss=0.f;
  float4 va = *(const float4*)(rp + t*4);
  float4 vb = *(const float4*)(rp + 1024 + t*4);
  s  = va.x+va.y+va.z+va.w + vb.x+vb.y+vb.z+vb.w;
  ss = va.x*va.x+va.y*va.y+va.z*va.z+va.w*va.w
     + vb.x*vb.x+vb.y*vb.y+vb.z*vb.z+vb.w*vb.w;
  #pragma unroll
  for (int o=16;o;o>>=1){ s += __shfl_xor_sync(~0u,s,o); ss += __shfl_xor_sync(~0u,ss,o); }
  __shared__ float sw[8], ssw[8];
  int wid=t>>5, lane=t&31;
  if (lane==0){ sw[wid]=s; ssw[wid]=ss; }
  __syncthreads();
  float ts=0.f, tss=0.f;
  #pragma unroll
  for (int i2=0;i2<8;i2++){ ts+=sw[i2]; tss+=ssw[i2]; }
  float mu = ts*(1.f/CDIM);
  float rstd = rsqrtf(tss*(1.f/CDIM) - mu*mu + EPSV);
  __half* op = g_Yh + (size_t)row*CDIM;
  {
    int c = t*4;
    const float4* wp = (const float4*)(w + c);
    const float4* bp = (const float4*)(bias + c);
    float4 wv = *wp, bv = *bp;
    __half2 h0 = __floats2half2_rn((va.x-mu)*rstd*wv.x + bv.x, (va.y-mu)*rstd*wv.y + bv.y);
    __half2 h1 = __floats2half2_rn((va.z-mu)*rstd*wv.z + bv.z, (va.w-mu)*rstd*wv.w + bv.w);
    *(__half2*)(op + c)     = h0;
    *(__half2*)(op + c + 2) = h1;
    c = 1024 + t*4;
    wv = *(const float4*)(w + c); bv = *(const float4*)(bias + c);
    h0 = __floats2half2_rn((vb.x-mu)*rstd*wv.x + bv.x, (vb.y-mu)*rstd*wv.y + bv.y);
    h1 = __floats2half2_rn((vb.z-mu)*rstd*wv.z + bv.z, (vb.w-mu)*rstd*wv.w + bv.w);
    *(__half2*)(op + c)     = h0;
    *(__half2*)(op + c + 2) = h1;
  }
}

// ============================================================
extern "C" void kernel_launch(void* const* d_in, const int* in_sizes, int n_in,
                              void* d_out, int out_size)
{
  const float* H   = (const float*)d_in[0];
  const int*   pid = (const int*)  d_in[1];
  const float* Wq  = (const float*)d_in[2];
  const float* Wk  = (const float*)d_in[3];
  const float* Wv  = (const float*)d_in[4];
  const float* Wo  = (const float*)d_in[5];
  const float* W1  = (const float*)d_in[6];
  const float* b1  = (const float*)d_in[7];
  const float* lrw = (const float*)d_in[8];
  const float* lrb = (const float*)d_in[9];
  const float* lti = (const float*)d_in[10];
  const float* lnw = (const float*)d_in[11];
  const float* lnb = (const float*)d_in[12];
  const float* pnw = (const float*)d_in[13];
  const float* pnb = (const float*)d_in[14];
  float* out = (float*)d_out;
  (void)in_sizes; (void)n_in; (void)out_size;

  static bool inited = false;
  static cudaStream_t s2;
  static cudaEvent_t evFork, evJoin;
  if (!inited){
    cudaFuncSetAttribute(gemm_qkv_f16, cudaFuncAttributeMaxDynamicSharedMemorySize, SM_G(128));
    cudaFuncSetAttribute(gemm_out_f16, cudaFuncAttributeMaxDynamicSharedMemorySize, SM_G(64));
    cudaFuncSetAttribute(ttt_scan,     cudaFuncAttributeMaxDynamicSharedMemorySize, SCAN_SM);
    cudaStreamCreateWithFlags(&s2, cudaStreamNonBlocking);
    cudaEventCreateWithFlags(&evFork, cudaEventDisableTiming);
    cudaEventCreateWithFlags(&evJoin, cudaEventDisableTiming);
    inited = true;
  }

  __half* wth = nullptr; cudaGetSymbolAddress((void**)&wth, g_wth);
  __half* woh = nullptr; cudaGetSymbolAddress((void**)&woh, g_woh);

  // fork: lr_gemm on s2 (independent of QKV; overlaps with prep + QKV)
  cudaEventRecord(evFork, 0);
  cudaStreamWaitEvent(s2, evFork, 0);
  lr_gemm<<<BL/64, 256, 0, s2>>>(H, lrw);
  cudaEventRecord(evJoin, s2);

  transpose_h<<<dim3(64,64), 256>>>(Wq, wth,                        CDIM, CDIM);
  transpose_h<<<dim3(64,64), 256>>>(Wk, wth + (size_t)CDIM*CDIM,    CDIM, CDIM);
  transpose_h<<<dim3(64,64), 256>>>(Wv, wth + (size_t)2*CDIM*CDIM,  CDIM, CDIM);
  transpose_h<<<dim3(24,64), 256>>>(Wo, woh,                        CDIM, ODIM);
  half_H<<<(BL*(size_t)CDIM)/(256*4), 256>>>(H);

  gemm_qkv_f16<<<dim3(24, BL/128), 256, SM_G(128)>>>();

  // join lr before scan (scan reads g_lr)
  cudaStreamWaitEvent(0, evJoin, 0);
  ttt_scan<<<BDIM*NHEADS, 256, SCAN_SM>>>(pid, W1, b1, lrb, lti, lnw, lnb);
  rownorm<<<BL, 256>>>(pnw, pnb);
  gemm_out_f16<<<dim3(ODIM/256, BL/64), 256, SM_G(64)>>>(out);
}